// round 1
// baseline (speedup 1.0000x reference)
#include <cuda_runtime.h>
#include <math.h>

// Problem constants (from reference setup_inputs)
#define Bq 4
#define Lq 8192
#define Dq 512
#define Hq 1024
#define Mq (Bq*Lq)        // 32768 rows (B*L flattened)

#define NCHUNK 128
#define CLEN (Lq/NCHUNK)  // 64

// Scratch (device globals; allocation in kernel_launch is forbidden)
__device__ float g_c [Bq*Lq*Hq];   // coefficient  sigmoid(-gate)
__device__ float g_zg[Bq*Lq*Hq];   // z * g~       sigmoid(gate)*g(hidden)
__device__ float g_h [Bq*Lq*Hq];   // scan output
__device__ float g_A [Bq*NCHUNK*Hq];
__device__ float g_Bc[Bq*NCHUNK*Hq];
__device__ float g_hs[Bq*NCHUNK*Hq];

#define BM 128
#define BN 128
#define BK 16

// ---------------------------------------------------------------------------
// K1: hg = x @ W_in^T + b_in, fused activation epilogue.
// Block computes a 128(M) x 128(col) tile where col j maps to:
//   channel ch0 + (j>>1), part (j&1): 0 = hidden row of W_in, 1 = gate row.
// This keeps each thread's 8 consecutive cols = 4 (hidden,gate) pairs, so the
// epilogue can emit float4 stores of c and z*g~ per 4 consecutive channels.
// ---------------------------------------------------------------------------
__global__ __launch_bounds__(256, 2)
void gemm1_act(const float* __restrict__ X, const float* __restrict__ Win,
               const float* __restrict__ bin)
{
    __shared__ float As[BK][BM+4];
    __shared__ float Bs[BK][BN+4];
    const int tid = threadIdx.x;
    const int tx = tid & 15, ty = tid >> 4;
    const int m0 = blockIdx.x * BM;
    const int ch0 = blockIdx.y * (BN/2);   // 64 channels per block

    float acc[8][8];
    #pragma unroll
    for (int i = 0; i < 8; i++)
        #pragma unroll
        for (int j = 0; j < 8; j++) acc[i][j] = 0.f;

    for (int k0 = 0; k0 < Dq; k0 += BK) {
        #pragma unroll
        for (int i = 0; i < 2; i++) {
            int id  = tid + 256*i;
            int row = id >> 2;
            int kv  = (id & 3) * 4;
            float4 v = *(const float4*)(X + (size_t)(m0+row)*Dq + k0 + kv);
            As[kv+0][row] = v.x; As[kv+1][row] = v.y;
            As[kv+2][row] = v.z; As[kv+3][row] = v.w;
            int j = row;
            int wrow = (j & 1) ? (Hq + ch0 + (j>>1)) : (ch0 + (j>>1));
            float4 w = *(const float4*)(Win + (size_t)wrow*Dq + k0 + kv);
            Bs[kv+0][j] = w.x; Bs[kv+1][j] = w.y;
            Bs[kv+2][j] = w.z; Bs[kv+3][j] = w.w;
        }
        __syncthreads();
        #pragma unroll
        for (int kk = 0; kk < BK; kk++) {
            float a[8], b[8];
            *(float4*)&a[0] = *(const float4*)&As[kk][ty*8];
            *(float4*)&a[4] = *(const float4*)&As[kk][ty*8+4];
            *(float4*)&b[0] = *(const float4*)&Bs[kk][tx*8];
            *(float4*)&b[4] = *(const float4*)&Bs[kk][tx*8+4];
            #pragma unroll
            for (int i = 0; i < 8; i++)
                #pragma unroll
                for (int j = 0; j < 8; j++)
                    acc[i][j] += a[i]*b[j];
        }
        __syncthreads();
    }

    const int chBase = ch0 + tx*4;
    float bh[4], bg[4];
    #pragma unroll
    for (int q = 0; q < 4; q++) { bh[q] = bin[chBase+q]; bg[q] = bin[Hq+chBase+q]; }

    #pragma unroll
    for (int i = 0; i < 8; i++) {
        int row = m0 + ty*8 + i;
        float4 cv, zv;
        float* cp = &cv.x; float* zp = &zv.x;
        #pragma unroll
        for (int q = 0; q < 4; q++) {
            float hid = acc[i][2*q]   + bh[q];
            float gat = acc[i][2*q+1] + bg[q];
            float z  = 1.f/(1.f + __expf(-gat));          // sigmoid(gate)
            float cc = 1.f/(1.f + __expf( gat));          // sigmoid(-gate)
            float gt = (hid >= 0.f) ? (hid + 0.5f)
                                    : (1.f/(1.f + __expf(-hid)));
            cp[q] = cc;
            zp[q] = z * gt;
        }
        *(float4*)(g_c  + (size_t)row*Hq + chBase) = cv;
        *(float4*)(g_zg + (size_t)row*Hq + chBase) = zv;
    }
}

// ---------------------------------------------------------------------------
// K2: per-chunk affine composition (h_end = A * h_start + B), h_start = 0.
// Coalesced: consecutive threads = consecutive channels.
// ---------------------------------------------------------------------------
__global__ void scan_chunks()
{
    int h = blockIdx.x*256 + threadIdx.x;
    int chunk = blockIdx.y, b = blockIdx.z;
    size_t base = ((size_t)b*Lq + (size_t)chunk*CLEN)*Hq + h;
    float A = 1.f, Bv = 0.f;
    #pragma unroll 8
    for (int t = 0; t < CLEN; t++) {
        float c = g_c[base], z = g_zg[base];
        Bv = c*Bv + z;
        A *= c;
        base += Hq;
    }
    size_t o = ((size_t)b*NCHUNK + chunk)*Hq + h;
    g_A[o] = A; g_Bc[o] = Bv;
}

// K3: sequential scan over the 128 chunk compositions, per channel.
__global__ void scan_tops()
{
    int g = blockIdx.x*256 + threadIdx.x;   // 0..4095
    int b = g >> 10, hh = g & 1023;
    float hs = 0.f;
    size_t o = ((size_t)b*NCHUNK)*Hq + hh;
    for (int i = 0; i < NCHUNK; i++) {
        g_hs[o] = hs;
        hs = g_A[o]*hs + g_Bc[o];
        o += Hq;
    }
}

// K4: re-run each chunk's recurrence from its true h_start, write h.
__global__ void scan_apply()
{
    int h = blockIdx.x*256 + threadIdx.x;
    int chunk = blockIdx.y, b = blockIdx.z;
    float hs = g_hs[((size_t)b*NCHUNK + chunk)*Hq + h];
    size_t base = ((size_t)b*Lq + (size_t)chunk*CLEN)*Hq + h;
    #pragma unroll 8
    for (int t = 0; t < CLEN; t++) {
        float c = g_c[base], z = g_zg[base];
        hs = c*hs + z;
        g_h[base] = hs;
        base += Hq;
    }
}

// ---------------------------------------------------------------------------
// K5: out = h @ W_out^T + b_out.  M=32768, N=512, K=1024.
// ---------------------------------------------------------------------------
__global__ __launch_bounds__(256, 2)
void gemm2(const float* __restrict__ Wout, const float* __restrict__ bout,
           float* __restrict__ Out)
{
    __shared__ float As[BK][BM+4];
    __shared__ float Bs[BK][BN+4];
    const int tid = threadIdx.x;
    const int tx = tid & 15, ty = tid >> 4;
    const int m0 = blockIdx.x * BM;
    const int n0 = blockIdx.y * BN;

    float acc[8][8];
    #pragma unroll
    for (int i = 0; i < 8; i++)
        #pragma unroll
        for (int j = 0; j < 8; j++) acc[i][j] = 0.f;

    for (int k0 = 0; k0 < Hq; k0 += BK) {
        #pragma unroll
        for (int i = 0; i < 2; i++) {
            int id  = tid + 256*i;
            int row = id >> 2;
            int kv  = (id & 3) * 4;
            float4 v = *(const float4*)(g_h + (size_t)(m0+row)*Hq + k0 + kv);
            As[kv+0][row] = v.x; As[kv+1][row] = v.y;
            As[kv+2][row] = v.z; As[kv+3][row] = v.w;
            float4 w = *(const float4*)(Wout + (size_t)(n0+row)*Hq + k0 + kv);
            Bs[kv+0][row] = w.x; Bs[kv+1][row] = w.y;
            Bs[kv+2][row] = w.z; Bs[kv+3][row] = w.w;
        }
        __syncthreads();
        #pragma unroll
        for (int kk = 0; kk < BK; kk++) {
            float a[8], b[8];
            *(float4*)&a[0] = *(const float4*)&As[kk][ty*8];
            *(float4*)&a[4] = *(const float4*)&As[kk][ty*8+4];
            *(float4*)&b[0] = *(const float4*)&Bs[kk][tx*8];
            *(float4*)&b[4] = *(const float4*)&Bs[kk][tx*8+4];
            #pragma unroll
            for (int i = 0; i < 8; i++)
                #pragma unroll
                for (int j = 0; j < 8; j++)
                    acc[i][j] += a[i]*b[j];
        }
        __syncthreads();
    }

    const int colBase = n0 + tx*8;
    float bo[8];
    #pragma unroll
    for (int q = 0; q < 8; q++) bo[q] = bout[colBase+q];

    #pragma unroll
    for (int i = 0; i < 8; i++) {
        int row = m0 + ty*8 + i;
        float4 o0, o1;
        o0.x = acc[i][0]+bo[0]; o0.y = acc[i][1]+bo[1];
        o0.z = acc[i][2]+bo[2]; o0.w = acc[i][3]+bo[3];
        o1.x = acc[i][4]+bo[4]; o1.y = acc[i][5]+bo[5];
        o1.z = acc[i][6]+bo[6]; o1.w = acc[i][7]+bo[7];
        *(float4*)(Out + (size_t)row*Dq + colBase)     = o0;
        *(float4*)(Out + (size_t)row*Dq + colBase + 4) = o1;
    }
}

// ---------------------------------------------------------------------------
extern "C" void kernel_launch(void* const* d_in, const int* in_sizes, int n_in,
                              void* d_out, int out_size)
{
    const float *x = nullptr, *win = nullptr, *bin = nullptr,
                *wout = nullptr, *bout = nullptr;
    // Identify inputs by element count (all distinct) — robust to ordering.
    for (int i = 0; i < n_in; i++) {
        switch (in_sizes[i]) {
            case Bq*Lq*Dq: x    = (const float*)d_in[i]; break; // 16777216
            case 2*Hq*Dq:  win  = (const float*)d_in[i]; break; // 1048576
            case 2*Hq:     bin  = (const float*)d_in[i]; break; // 2048
            case Dq*Hq:    wout = (const float*)d_in[i]; break; // 524288
            case Dq:       bout = (const float*)d_in[i]; break; // 512
        }
    }
    float* out = (float*)d_out;

    gemm1_act  <<<dim3(Mq/BM, Hq/(BN/2)), 256>>>(x, win, bin);
    scan_chunks<<<dim3(Hq/256, NCHUNK, Bq), 256>>>();
    scan_tops  <<<16, 256>>>();
    scan_apply <<<dim3(Hq/256, NCHUNK, Bq), 256>>>();
    gemm2      <<<dim3(Mq/BM, Dq/BN), 256>>>(wout, bout, out);
}

// round 3
// speedup vs baseline: 1.9836x; 1.9836x over previous
#include <cuda_runtime.h>
#include <cuda_bf16.h>
#include <math.h>

// Problem constants
#define Bq 4
#define Lq 8192
#define Dq 512
#define Hq 1024
#define Mq (Bq*Lq)        // 32768

#define NCHUNK 128
#define CLEN (Lq/NCHUNK)  // 64

// Scratch (device globals; allocation in kernel_launch is forbidden)
__device__ float g_c [Bq*Lq*Hq];
__device__ float g_zg[Bq*Lq*Hq];
__device__ float g_h [Bq*Lq*Hq];
__device__ float g_A [Bq*NCHUNK*Hq];
__device__ float g_Bc[Bq*NCHUNK*Hq];
__device__ float g_hs[Bq*NCHUNK*Hq];

#define BM 128
#define BN 128
#define BK 32
#define LDK 40   // smem row stride (bf16 elements)

// ---------------------------------------------------------------------------
// PTX helpers
// ---------------------------------------------------------------------------
#define LDSM_X4(r0,r1,r2,r3,addr) \
    asm volatile("ldmatrix.sync.aligned.m8n8.x4.shared.b16 {%0,%1,%2,%3}, [%4];" \
        : "=r"(r0),"=r"(r1),"=r"(r2),"=r"(r3) : "r"(addr))

#define MMA_BF16(c0,c1,c2,c3,a0,a1,a2,a3,b0,b1) \
    asm volatile("mma.sync.aligned.m16n8k16.row.col.f32.bf16.bf16.f32 " \
        "{%0,%1,%2,%3},{%4,%5,%6,%7},{%8,%9},{%0,%1,%2,%3};" \
        : "+f"(c0),"+f"(c1),"+f"(c2),"+f"(c3) \
        : "r"(a0),"r"(a1),"r"(a2),"r"(a3),"r"(b0),"r"(b1))

__device__ __forceinline__ unsigned short bf_us(__nv_bfloat16 h) {
    return *reinterpret_cast<unsigned short*>(&h);
}

// Convert float4 -> 4 hi bf16 (uint2) + 4 lo bf16 (uint2)
__device__ __forceinline__ void split4(float4 v, uint2& hi, uint2& lo) {
    __nv_bfloat16 hx = __float2bfloat16_rn(v.x);
    __nv_bfloat16 hy = __float2bfloat16_rn(v.y);
    __nv_bfloat16 hz = __float2bfloat16_rn(v.z);
    __nv_bfloat16 hw = __float2bfloat16_rn(v.w);
    __nv_bfloat16 lx = __float2bfloat16_rn(v.x - __bfloat162float(hx));
    __nv_bfloat16 ly = __float2bfloat16_rn(v.y - __bfloat162float(hy));
    __nv_bfloat16 lz = __float2bfloat16_rn(v.z - __bfloat162float(hz));
    __nv_bfloat16 lw = __float2bfloat16_rn(v.w - __bfloat162float(hw));
    hi.x = (unsigned)bf_us(hx) | ((unsigned)bf_us(hy) << 16);
    hi.y = (unsigned)bf_us(hz) | ((unsigned)bf_us(hw) << 16);
    lo.x = (unsigned)bf_us(lx) | ((unsigned)bf_us(ly) << 16);
    lo.y = (unsigned)bf_us(lz) | ((unsigned)bf_us(lw) << 16);
}

// ---------------------------------------------------------------------------
// K1: hg = x @ W_in^T + b_in (bf16-split tensor-core GEMM), fused activation.
// Columns j map to channel ch0+(j>>1); j&1 selects hidden(0)/gate(1) row of
// W_in, so each thread's (c0,c1) mma pair is one (hidden,gate) couple.
// ---------------------------------------------------------------------------
__global__ __launch_bounds__(256)
void gemm1_act(const float* __restrict__ X, const float* __restrict__ Win,
               const float* __restrict__ bin)
{
    __shared__ __nv_bfloat16 sAh[BM*LDK], sAl[BM*LDK];
    __shared__ __nv_bfloat16 sBh[BN*LDK], sBl[BN*LDK];

    const int tid  = threadIdx.x;
    const int lane = tid & 31;
    const int warp = tid >> 5;
    const int wm = (warp >> 1) * 32;      // warp m-offset (4 warps in m)
    const int wn = (warp & 1) * 64;       // warp n-offset (2 warps in n)
    const int m0 = blockIdx.x * BM;
    const int ch0 = blockIdx.y * (BN/2);

    unsigned sAh_u = (unsigned)__cvta_generic_to_shared(sAh);
    unsigned sAl_u = (unsigned)__cvta_generic_to_shared(sAl);
    unsigned sBh_u = (unsigned)__cvta_generic_to_shared(sBh);
    unsigned sBl_u = (unsigned)__cvta_generic_to_shared(sBl);

    float acc[2][8][4];
    #pragma unroll
    for (int i = 0; i < 2; i++)
        #pragma unroll
        for (int j = 0; j < 8; j++)
            #pragma unroll
            for (int q = 0; q < 4; q++) acc[i][j][q] = 0.f;

    for (int k0 = 0; k0 < Dq; k0 += BK) {
        // stage A and B tiles, converting f32 -> (hi,lo) bf16
        #pragma unroll
        for (int i = 0; i < 4; i++) {
            int id  = tid + 256*i;
            int row = id >> 3;
            int kv  = (id & 7) * 4;
            float4 v = *(const float4*)(X + (size_t)(m0+row)*Dq + k0 + kv);
            uint2 h, l; split4(v, h, l);
            *(uint2*)&sAh[row*LDK + kv] = h;
            *(uint2*)&sAl[row*LDK + kv] = l;
            int j = row;
            int wrow = (j & 1) ? (Hq + ch0 + (j>>1)) : (ch0 + (j>>1));
            float4 w = *(const float4*)(Win + (size_t)wrow*Dq + k0 + kv);
            uint2 wh, wl; split4(w, wh, wl);
            *(uint2*)&sBh[j*LDK + kv] = wh;
            *(uint2*)&sBl[j*LDK + kv] = wl;
        }
        __syncthreads();

        #pragma unroll
        for (int ks = 0; ks < BK; ks += 16) {
            // A fragments
            unsigned aH[2][4], aL[2][4];
            {
                int ar = (lane & 15);
                int ac = ks + 8*(lane >> 4);
                #pragma unroll
                for (int mi = 0; mi < 2; mi++) {
                    unsigned off = ((wm + mi*16 + ar)*LDK + ac) * 2;
                    LDSM_X4(aH[mi][0],aH[mi][1],aH[mi][2],aH[mi][3], sAh_u + off);
                    LDSM_X4(aL[mi][0],aL[mi][1],aL[mi][2],aL[mi][3], sAl_u + off);
                }
            }
            // B fragments: 8 n8-tiles, fetched as 4 x4-ldmatrix per split
            unsigned bH[8][2], bL[8][2];
            {
                int r  = lane & 7;
                int kc = ks + ((lane >> 3) & 1) * 8;
                int n8 = (lane >> 4) ? 8 : 0;
                #pragma unroll
                for (int p = 0; p < 4; p++) {
                    unsigned off = ((wn + p*16 + n8 + r)*LDK + kc) * 2;
                    LDSM_X4(bH[2*p][0],bH[2*p][1],bH[2*p+1][0],bH[2*p+1][1], sBh_u + off);
                    LDSM_X4(bL[2*p][0],bL[2*p][1],bL[2*p+1][0],bL[2*p+1][1], sBl_u + off);
                }
            }
            #pragma unroll
            for (int mi = 0; mi < 2; mi++)
                #pragma unroll
                for (int ni = 0; ni < 8; ni++) {
                    float* c = acc[mi][ni];
                    MMA_BF16(c[0],c[1],c[2],c[3],
                             aH[mi][0],aH[mi][1],aH[mi][2],aH[mi][3],
                             bH[ni][0],bH[ni][1]);
                    MMA_BF16(c[0],c[1],c[2],c[3],
                             aH[mi][0],aH[mi][1],aH[mi][2],aH[mi][3],
                             bL[ni][0],bL[ni][1]);
                    MMA_BF16(c[0],c[1],c[2],c[3],
                             aL[mi][0],aL[mi][1],aL[mi][2],aL[mi][3],
                             bH[ni][0],bH[ni][1]);
                }
        }
        __syncthreads();
    }

    // epilogue: activations
    #pragma unroll
    for (int ni = 0; ni < 8; ni++) {
        int nloc = wn + ni*8 + 2*(lane & 3);       // even
        int ch = ch0 + (nloc >> 1);
        float bh = bin[ch], bg = bin[Hq + ch];
        #pragma unroll
        for (int mi = 0; mi < 2; mi++) {
            float* c = acc[mi][ni];
            #pragma unroll
            for (int half = 0; half < 2; half++) {
                int row = m0 + wm + mi*16 + (lane >> 2) + half*8;
                float hid = c[2*half]   + bh;
                float gat = c[2*half+1] + bg;
                float z  = 1.f/(1.f + __expf(-gat));
                float cc = 1.f/(1.f + __expf( gat));
                float gt = (hid >= 0.f) ? (hid + 0.5f)
                                        : (1.f/(1.f + __expf(-hid)));
                g_c [(size_t)row*Hq + ch] = cc;
                g_zg[(size_t)row*Hq + ch] = z * gt;
            }
        }
    }
}

// ---------------------------------------------------------------------------
// K2-K4: chunked scan (unchanged)
// ---------------------------------------------------------------------------
__global__ void scan_chunks()
{
    int h = blockIdx.x*256 + threadIdx.x;
    int chunk = blockIdx.y, b = blockIdx.z;
    size_t base = ((size_t)b*Lq + (size_t)chunk*CLEN)*Hq + h;
    float A = 1.f, Bv = 0.f;
    #pragma unroll 8
    for (int t = 0; t < CLEN; t++) {
        float c = g_c[base], z = g_zg[base];
        Bv = c*Bv + z;
        A *= c;
        base += Hq;
    }
    size_t o = ((size_t)b*NCHUNK + chunk)*Hq + h;
    g_A[o] = A; g_Bc[o] = Bv;
}

__global__ void scan_tops()
{
    int g = blockIdx.x*256 + threadIdx.x;
    int b = g >> 10, hh = g & 1023;
    float hs = 0.f;
    size_t o = ((size_t)b*NCHUNK)*Hq + hh;
    for (int i = 0; i < NCHUNK; i++) {
        g_hs[o] = hs;
        hs = g_A[o]*hs + g_Bc[o];
        o += Hq;
    }
}

__global__ void scan_apply()
{
    int h = blockIdx.x*256 + threadIdx.x;
    int chunk = blockIdx.y, b = blockIdx.z;
    float hs = g_hs[((size_t)b*NCHUNK + chunk)*Hq + h];
    size_t base = ((size_t)b*Lq + (size_t)chunk*CLEN)*Hq + h;
    #pragma unroll 8
    for (int t = 0; t < CLEN; t++) {
        float c = g_c[base], z = g_zg[base];
        hs = c*hs + z;
        g_h[base] = hs;
        base += Hq;
    }
}

// ---------------------------------------------------------------------------
// K5: out = h @ W_out^T + b_out (bf16-split tensor-core GEMM)
// M=32768, N=512, K=1024
// ---------------------------------------------------------------------------
__global__ __launch_bounds__(256)
void gemm2(const float* __restrict__ Wout, const float* __restrict__ bout,
           float* __restrict__ Out)
{
    __shared__ __nv_bfloat16 sAh[BM*LDK], sAl[BM*LDK];
    __shared__ __nv_bfloat16 sBh[BN*LDK], sBl[BN*LDK];

    const int tid  = threadIdx.x;
    const int lane = tid & 31;
    const int warp = tid >> 5;
    const int wm = (warp >> 1) * 32;
    const int wn = (warp & 1) * 64;
    const int m0 = blockIdx.x * BM;
    const int n0 = blockIdx.y * BN;

    unsigned sAh_u = (unsigned)__cvta_generic_to_shared(sAh);
    unsigned sAl_u = (unsigned)__cvta_generic_to_shared(sAl);
    unsigned sBh_u = (unsigned)__cvta_generic_to_shared(sBh);
    unsigned sBl_u = (unsigned)__cvta_generic_to_shared(sBl);

    float acc[2][8][4];
    #pragma unroll
    for (int i = 0; i < 2; i++)
        #pragma unroll
        for (int j = 0; j < 8; j++)
            #pragma unroll
            for (int q = 0; q < 4; q++) acc[i][j][q] = 0.f;

    for (int k0 = 0; k0 < Hq; k0 += BK) {
        #pragma unroll
        for (int i = 0; i < 4; i++) {
            int id  = tid + 256*i;
            int row = id >> 3;
            int kv  = (id & 7) * 4;
            float4 v = *(const float4*)(g_h + (size_t)(m0+row)*Hq + k0 + kv);
            uint2 h, l; split4(v, h, l);
            *(uint2*)&sAh[row*LDK + kv] = h;
            *(uint2*)&sAl[row*LDK + kv] = l;
            float4 w = *(const float4*)(Wout + (size_t)(n0+row)*Hq + k0 + kv);
            uint2 wh, wl; split4(w, wh, wl);
            *(uint2*)&sBh[row*LDK + kv] = wh;
            *(uint2*)&sBl[row*LDK + kv] = wl;
        }
        __syncthreads();

        #pragma unroll
        for (int ks = 0; ks < BK; ks += 16) {
            unsigned aH[2][4], aL[2][4];
            {
                int ar = (lane & 15);
                int ac = ks + 8*(lane >> 4);
                #pragma unroll
                for (int mi = 0; mi < 2; mi++) {
                    unsigned off = ((wm + mi*16 + ar)*LDK + ac) * 2;
                    LDSM_X4(aH[mi][0],aH[mi][1],aH[mi][2],aH[mi][3], sAh_u + off);
                    LDSM_X4(aL[mi][0],aL[mi][1],aL[mi][2],aL[mi][3], sAl_u + off);
                }
            }
            unsigned bH[8][2], bL[8][2];
            {
                int r  = lane & 7;
                int kc = ks + ((lane >> 3) & 1) * 8;
                int n8 = (lane >> 4) ? 8 : 0;
                #pragma unroll
                for (int p = 0; p < 4; p++) {
                    unsigned off = ((wn + p*16 + n8 + r)*LDK + kc) * 2;
                    LDSM_X4(bH[2*p][0],bH[2*p][1],bH[2*p+1][0],bH[2*p+1][1], sBh_u + off);
                    LDSM_X4(bL[2*p][0],bL[2*p][1],bL[2*p+1][0],bL[2*p+1][1], sBl_u + off);
                }
            }
            #pragma unroll
            for (int mi = 0; mi < 2; mi++)
                #pragma unroll
                for (int ni = 0; ni < 8; ni++) {
                    float* c = acc[mi][ni];
                    MMA_BF16(c[0],c[1],c[2],c[3],
                             aH[mi][0],aH[mi][1],aH[mi][2],aH[mi][3],
                             bH[ni][0],bH[ni][1]);
                    MMA_BF16(c[0],c[1],c[2],c[3],
                             aH[mi][0],aH[mi][1],aH[mi][2],aH[mi][3],
                             bL[ni][0],bL[ni][1]);
                    MMA_BF16(c[0],c[1],c[2],c[3],
                             aL[mi][0],aL[mi][1],aL[mi][2],aL[mi][3],
                             bH[ni][0],bH[ni][1]);
                }
        }
        __syncthreads();
    }

    #pragma unroll
    for (int ni = 0; ni < 8; ni++) {
        int nd = n0 + wn + ni*8 + 2*(lane & 3);
        float b0 = bout[nd], b1 = bout[nd+1];
        #pragma unroll
        for (int mi = 0; mi < 2; mi++) {
            float* c = acc[mi][ni];
            #pragma unroll
            for (int half = 0; half < 2; half++) {
                int row = m0 + wm + mi*16 + (lane >> 2) + half*8;
                float2 o;
                o.x = c[2*half]   + b0;
                o.y = c[2*half+1] + b1;
                *(float2*)(Out + (size_t)row*Dq + nd) = o;
            }
        }
    }
}

// ---------------------------------------------------------------------------
extern "C" void kernel_launch(void* const* d_in, const int* in_sizes, int n_in,
                              void* d_out, int out_size)
{
    const float *x = nullptr, *win = nullptr, *bin = nullptr,
                *wout = nullptr, *bout = nullptr;
    for (int i = 0; i < n_in; i++) {
        switch (in_sizes[i]) {
            case Bq*Lq*Dq: x    = (const float*)d_in[i]; break;
            case 2*Hq*Dq:  win  = (const float*)d_in[i]; break;
            case 2*Hq:     bin  = (const float*)d_in[i]; break;
            case Dq*Hq:    wout = (const float*)d_in[i]; break;
            case Dq:       bout = (const float*)d_in[i]; break;
        }
    }
    float* out = (float*)d_out;

    gemm1_act  <<<dim3(Mq/BM, Hq/(BN/2)), 256>>>(x, win, bin);
    scan_chunks<<<dim3(Hq/256, NCHUNK, Bq), 256>>>();
    scan_tops  <<<16, 256>>>();
    scan_apply <<<dim3(Hq/256, NCHUNK, Bq), 256>>>();
    gemm2      <<<dim3(Mq/BM, Dq/BN), 256>>>(wout, bout, out);
}

// round 6
// speedup vs baseline: 2.0427x; 1.0298x over previous
#include <cuda_runtime.h>
#include <cuda_bf16.h>
#include <cstdint>

// Problem constants
#define Bq 4
#define Lq 8192
#define Dq 512
#define Hq 1024
#define Mq (Bq*Lq)        // 32768
#define NCHUNK 128
#define CLEN 64

// ---------------------------------------------------------------------------
// Scratch (device globals; allocation is forbidden)
// ---------------------------------------------------------------------------
__device__ float g_c [Bq*Lq*Hq];
__device__ float g_zg[Bq*Lq*Hq];
__device__ float g_A [Bq*NCHUNK*Hq];
__device__ float g_Bc[Bq*NCHUNK*Hq];
__device__ float g_hs[Bq*NCHUNK*Hq];
__device__ __nv_bfloat16 g_xh[(size_t)Mq*Dq], g_xl[(size_t)Mq*Dq];
__device__ __nv_bfloat16 g_wih[2*Hq*Dq],      g_wil[2*Hq*Dq];
__device__ __nv_bfloat16 g_woh[Dq*Hq],        g_wol[Dq*Hq];
__device__ __nv_bfloat16 g_hh[(size_t)Mq*Hq], g_hl[(size_t)Mq*Hq];

// ---------------------------------------------------------------------------
// PTX helpers
// ---------------------------------------------------------------------------
__device__ __forceinline__ uint32_t s2u(const void* p) {
    uint32_t a;
    asm("{ .reg .u64 t; cvta.to.shared.u64 t, %1; cvt.u32.u64 %0, t; }"
        : "=r"(a) : "l"(p));
    return a;
}
#define LDSM_X4(r0,r1,r2,r3,addr) \
    asm volatile("ldmatrix.sync.aligned.m8n8.x4.shared.b16 {%0,%1,%2,%3}, [%4];" \
        : "=r"(r0),"=r"(r1),"=r"(r2),"=r"(r3) : "r"(addr))

#define MMA_BF16(c0,c1,c2,c3,a0,a1,a2,a3,b0,b1) \
    asm volatile("mma.sync.aligned.m16n8k16.row.col.f32.bf16.bf16.f32 " \
        "{%0,%1,%2,%3},{%4,%5,%6,%7},{%8,%9},{%0,%1,%2,%3};" \
        : "+f"(c0),"+f"(c1),"+f"(c2),"+f"(c3) \
        : "r"(a0),"r"(a1),"r"(a2),"r"(a3),"r"(b0),"r"(b1))

__device__ __forceinline__ void cpa16(uint32_t dst, const void* src) {
    asm volatile("cp.async.cg.shared.global [%0], [%1], 16;"
                 :: "r"(dst), "l"(src));
}
#define CP_COMMIT() asm volatile("cp.async.commit_group;")
#define CP_WAIT2()  asm volatile("cp.async.wait_group 2;")
#define CP_WAIT1()  asm volatile("cp.async.wait_group 1;")
#define CP_WAIT0()  asm volatile("cp.async.wait_group 0;")

// smem: 3 stages x (4 tiles of 128 rows x 72 bf16)
#define LDK 72
#define TILE_B (128*LDK*2)    // 18432
#define STAGE_B (4*TILE_B)    // 73728
#define STAGES 3
#define SMEM_TOTAL (STAGES*STAGE_B)  // 221184

// ---------------------------------------------------------------------------
// split: f32 -> (hi, lo) bf16
// ---------------------------------------------------------------------------
__device__ __forceinline__ unsigned short bfu(__nv_bfloat16 h) {
    return *reinterpret_cast<unsigned short*>(&h);
}
__global__ void split_f32(const float* __restrict__ s,
                          __nv_bfloat16* __restrict__ hi,
                          __nv_bfloat16* __restrict__ lo, int n4)
{
    int i = blockIdx.x * blockDim.x + threadIdx.x;
    if (i >= n4) return;
    float4 v = ((const float4*)s)[i];
    __nv_bfloat16 hx = __float2bfloat16_rn(v.x);
    __nv_bfloat16 hy = __float2bfloat16_rn(v.y);
    __nv_bfloat16 hz = __float2bfloat16_rn(v.z);
    __nv_bfloat16 hw = __float2bfloat16_rn(v.w);
    uint2 H, L;
    H.x = (unsigned)bfu(hx) | ((unsigned)bfu(hy) << 16);
    H.y = (unsigned)bfu(hz) | ((unsigned)bfu(hw) << 16);
    __nv_bfloat16 lx = __float2bfloat16_rn(v.x - __bfloat162float(hx));
    __nv_bfloat16 ly = __float2bfloat16_rn(v.y - __bfloat162float(hy));
    __nv_bfloat16 lz = __float2bfloat16_rn(v.z - __bfloat162float(hz));
    __nv_bfloat16 lw = __float2bfloat16_rn(v.w - __bfloat162float(hw));
    L.x = (unsigned)bfu(lx) | ((unsigned)bfu(ly) << 16);
    L.y = (unsigned)bfu(lz) | ((unsigned)bfu(lw) << 16);
    ((uint2*)hi)[i] = H;
    ((uint2*)lo)[i] = L;
}

// ---------------------------------------------------------------------------
// MMA consume for one 64-wide K stage (shared by both GEMMs)
// ---------------------------------------------------------------------------
__device__ __forceinline__ void mma_stage(uint32_t bb, int lane, int wm, int wn,
                                          float acc[2][8][4])
{
    #pragma unroll
    for (int ks = 0; ks < 4; ks++) {
        int kk = ks * 16;
        unsigned aH[2][4], aL[2][4];
        {
            int ar = lane & 15;
            int ac = kk + 8 * (lane >> 4);
            #pragma unroll
            for (int mi = 0; mi < 2; mi++) {
                unsigned off = ((wm + mi*16 + ar) * LDK + ac) * 2;
                LDSM_X4(aH[mi][0],aH[mi][1],aH[mi][2],aH[mi][3], bb + off);
                LDSM_X4(aL[mi][0],aL[mi][1],aL[mi][2],aL[mi][3], bb + TILE_B + off);
            }
        }
        unsigned bH[8][2], bL[8][2];
        {
            int r  = lane & 7;
            int kc = kk + ((lane >> 3) & 1) * 8;
            int n8 = (lane >> 4) ? 8 : 0;
            #pragma unroll
            for (int p = 0; p < 4; p++) {
                unsigned off = ((wn + p*16 + n8 + r) * LDK + kc) * 2;
                LDSM_X4(bH[2*p][0],bH[2*p][1],bH[2*p+1][0],bH[2*p+1][1],
                        bb + 2*TILE_B + off);
                LDSM_X4(bL[2*p][0],bL[2*p][1],bL[2*p+1][0],bL[2*p+1][1],
                        bb + 3*TILE_B + off);
            }
        }
        #pragma unroll
        for (int mi = 0; mi < 2; mi++)
            #pragma unroll
            for (int ni = 0; ni < 8; ni++) {
                float* c = acc[mi][ni];
                MMA_BF16(c[0],c[1],c[2],c[3],
                         aH[mi][0],aH[mi][1],aH[mi][2],aH[mi][3],
                         bH[ni][0],bH[ni][1]);
                MMA_BF16(c[0],c[1],c[2],c[3],
                         aH[mi][0],aH[mi][1],aH[mi][2],aH[mi][3],
                         bL[ni][0],bL[ni][1]);
                MMA_BF16(c[0],c[1],c[2],c[3],
                         aL[mi][0],aL[mi][1],aL[mi][2],aL[mi][3],
                         bH[ni][0],bH[ni][1]);
            }
    }
}

__device__ __forceinline__ void pipe_wait(int rem)
{
    if (rem >= 2)      { CP_WAIT2(); }
    else if (rem == 1) { CP_WAIT1(); }
    else               { CP_WAIT0(); }
}

// ---------------------------------------------------------------------------
// K1: gemm1 (x @ W_in^T) + activation epilogue. Tile 128m x 128col, K=512.
// Col j -> channel ch0+(j>>1); j&1: 0=hidden W row, 1=gate W row.
// ---------------------------------------------------------------------------
__global__ __launch_bounds__(256)
void gemm1_tc(const float* __restrict__ bin)
{
    extern __shared__ char smem[];
    uint32_t su = s2u(smem);
    const int tid = threadIdx.x;
    const int lane = tid & 31;
    const int warp = tid >> 5;
    const int wm = (warp >> 1) * 32;
    const int wn = (warp & 1) * 64;
    const int m0 = blockIdx.x * 128;
    const int ch0 = blockIdx.y * 64;
    const int NC = Dq / 64;   // 8

    float acc[2][8][4];
    #pragma unroll
    for (int i = 0; i < 2; i++)
        #pragma unroll
        for (int j = 0; j < 8; j++)
            #pragma unroll
            for (int q = 0; q < 4; q++) acc[i][j][q] = 0.f;

    auto stage = [&](int c) {
        uint32_t bb = su + (c % STAGES) * STAGE_B;
        int k0 = c * 64;
        #pragma unroll
        for (int i = 0; i < 4; i++) {
            int id = tid + 256 * i;
            int row = id >> 3, c16 = id & 7;
            uint32_t off = (uint32_t)(row * (LDK*2) + c16 * 16);
            size_t ai = (size_t)(m0 + row) * Dq + k0 + c16 * 8;
            cpa16(bb + off,            g_xh + ai);
            cpa16(bb + TILE_B + off,   g_xl + ai);
            int wrow = (row & 1) ? (Hq + ch0 + (row >> 1)) : (ch0 + (row >> 1));
            size_t bi = (size_t)wrow * Dq + k0 + c16 * 8;
            cpa16(bb + 2*TILE_B + off, g_wih + bi);
            cpa16(bb + 3*TILE_B + off, g_wil + bi);
        }
        CP_COMMIT();
    };

    stage(0); stage(1); stage(2);
    for (int c = 0; c < NC; c++) {
        pipe_wait(NC - 1 - c < STAGES-1 ? NC - 1 - c : STAGES-1);
        __syncthreads();
        mma_stage(su + (c % STAGES) * STAGE_B, lane, wm, wn, acc);
        __syncthreads();
        if (c + STAGES < NC) stage(c + STAGES);
    }

    // epilogue: activations
    #pragma unroll
    for (int ni = 0; ni < 8; ni++) {
        int nloc = wn + ni*8 + 2*(lane & 3);
        int ch = ch0 + (nloc >> 1);
        float bh = bin[ch], bg = bin[Hq + ch];
        #pragma unroll
        for (int mi = 0; mi < 2; mi++) {
            float* c = acc[mi][ni];
            #pragma unroll
            for (int half = 0; half < 2; half++) {
                int row = m0 + wm + mi*16 + (lane >> 2) + half*8;
                float hid = c[2*half]   + bh;
                float gat = c[2*half+1] + bg;
                float z  = 1.f/(1.f + __expf(-gat));
                float cc = 1.f - z;
                float gt = (hid >= 0.f) ? (hid + 0.5f)
                                        : (1.f/(1.f + __expf(-hid)));
                g_c [(size_t)row*Hq + ch] = cc;
                g_zg[(size_t)row*Hq + ch] = z * gt;
            }
        }
    }
}

// ---------------------------------------------------------------------------
// K2-K4: chunked scan
// ---------------------------------------------------------------------------
__global__ void scan_chunks()
{
    int h = blockIdx.x*256 + threadIdx.x;
    int chunk = blockIdx.y, b = blockIdx.z;
    size_t base = ((size_t)b*Lq + (size_t)chunk*CLEN)*Hq + h;
    float A = 1.f, Bv = 0.f;
    #pragma unroll 8
    for (int t = 0; t < CLEN; t++) {
        float c = g_c[base], z = g_zg[base];
        Bv = c*Bv + z;
        A *= c;
        base += Hq;
    }
    size_t o = ((size_t)b*NCHUNK + chunk)*Hq + h;
    g_A[o] = A; g_Bc[o] = Bv;
}

__global__ void scan_tops()
{
    int g = blockIdx.x*256 + threadIdx.x;
    int b = g >> 10, hh = g & 1023;
    float hs = 0.f;
    size_t o = ((size_t)b*NCHUNK)*Hq + hh;
    for (int i = 0; i < NCHUNK; i++) {
        g_hs[o] = hs;
        hs = g_A[o]*hs + g_Bc[o];
        o += Hq;
    }
}

__global__ void scan_apply()
{
    int h = blockIdx.x*256 + threadIdx.x;
    int chunk = blockIdx.y, b = blockIdx.z;
    float hs = g_hs[((size_t)b*NCHUNK + chunk)*Hq + h];
    size_t base = ((size_t)b*Lq + (size_t)chunk*CLEN)*Hq + h;
    #pragma unroll 8
    for (int t = 0; t < CLEN; t++) {
        float c = g_c[base], z = g_zg[base];
        hs = c*hs + z;
        __nv_bfloat16 hi = __float2bfloat16_rn(hs);
        g_hh[base] = hi;
        g_hl[base] = __float2bfloat16_rn(hs - __bfloat162float(hi));
        base += Hq;
    }
}

// ---------------------------------------------------------------------------
// K5: gemm2 (h @ W_out^T + b_out). M=32768, N=512, K=1024.
// ---------------------------------------------------------------------------
__global__ __launch_bounds__(256)
void gemm2_tc(const float* __restrict__ bout, float* __restrict__ Out)
{
    extern __shared__ char smem[];
    uint32_t su = s2u(smem);
    const int tid = threadIdx.x;
    const int lane = tid & 31;
    const int warp = tid >> 5;
    const int wm = (warp >> 1) * 32;
    const int wn = (warp & 1) * 64;
    const int m0 = blockIdx.x * 128;
    const int n0 = blockIdx.y * 128;
    const int NC = Hq / 64;   // 16

    float acc[2][8][4];
    #pragma unroll
    for (int i = 0; i < 2; i++)
        #pragma unroll
        for (int j = 0; j < 8; j++)
            #pragma unroll
            for (int q = 0; q < 4; q++) acc[i][j][q] = 0.f;

    auto stage = [&](int c) {
        uint32_t bb = su + (c % STAGES) * STAGE_B;
        int k0 = c * 64;
        #pragma unroll
        for (int i = 0; i < 4; i++) {
            int id = tid + 256 * i;
            int row = id >> 3, c16 = id & 7;
            uint32_t off = (uint32_t)(row * (LDK*2) + c16 * 16);
            size_t ai = (size_t)(m0 + row) * Hq + k0 + c16 * 8;
            cpa16(bb + off,            g_hh + ai);
            cpa16(bb + TILE_B + off,   g_hl + ai);
            size_t bi = (size_t)(n0 + row) * Hq + k0 + c16 * 8;
            cpa16(bb + 2*TILE_B + off, g_woh + bi);
            cpa16(bb + 3*TILE_B + off, g_wol + bi);
        }
        CP_COMMIT();
    };

    stage(0); stage(1); stage(2);
    for (int c = 0; c < NC; c++) {
        pipe_wait(NC - 1 - c < STAGES-1 ? NC - 1 - c : STAGES-1);
        __syncthreads();
        mma_stage(su + (c % STAGES) * STAGE_B, lane, wm, wn, acc);
        __syncthreads();
        if (c + STAGES < NC) stage(c + STAGES);
    }

    #pragma unroll
    for (int ni = 0; ni < 8; ni++) {
        int nd = n0 + wn + ni*8 + 2*(lane & 3);
        float b0 = bout[nd], b1 = bout[nd+1];
        #pragma unroll
        for (int mi = 0; mi < 2; mi++) {
            float* c = acc[mi][ni];
            #pragma unroll
            for (int half = 0; half < 2; half++) {
                int row = m0 + wm + mi*16 + (lane >> 2) + half*8;
                float2 o;
                o.x = c[2*half]   + b0;
                o.y = c[2*half+1] + b1;
                *(float2*)(Out + (size_t)row*Dq + nd) = o;
            }
        }
    }
}

// ---------------------------------------------------------------------------
extern "C" void kernel_launch(void* const* d_in, const int* in_sizes, int n_in,
                              void* d_out, int out_size)
{
    const float *x = nullptr, *win = nullptr, *bin = nullptr,
                *wout = nullptr, *bout = nullptr;
    for (int i = 0; i < n_in; i++) {
        switch (in_sizes[i]) {
            case Bq*Lq*Dq: x    = (const float*)d_in[i]; break;
            case 2*Hq*Dq:  win  = (const float*)d_in[i]; break;
            case 2*Hq:     bin  = (const float*)d_in[i]; break;
            case Dq*Hq:    wout = (const float*)d_in[i]; break;
            case Dq:       bout = (const float*)d_in[i]; break;
        }
    }
    float* out = (float*)d_out;

    static bool attr_done = false;
    if (!attr_done) {
        cudaFuncSetAttribute(gemm1_tc, cudaFuncAttributeMaxDynamicSharedMemorySize, SMEM_TOTAL);
        cudaFuncSetAttribute(gemm2_tc, cudaFuncAttributeMaxDynamicSharedMemorySize, SMEM_TOTAL);
        attr_done = true;
    }

    __nv_bfloat16 *xh, *xl, *wih, *wil, *woh, *wol;
    cudaGetSymbolAddress((void**)&xh,  g_xh);
    cudaGetSymbolAddress((void**)&xl,  g_xl);
    cudaGetSymbolAddress((void**)&wih, g_wih);
    cudaGetSymbolAddress((void**)&wil, g_wil);
    cudaGetSymbolAddress((void**)&woh, g_woh);
    cudaGetSymbolAddress((void**)&wol, g_wol);

    split_f32<<<(Mq*Dq/4 + 255)/256, 256>>>(x, xh, xl, Mq*Dq/4);
    split_f32<<<(2*Hq*Dq/4 + 255)/256, 256>>>(win, wih, wil, 2*Hq*Dq/4);
    split_f32<<<(Dq*Hq/4 + 255)/256, 256>>>(wout, woh, wol, Dq*Hq/4);

    gemm1_tc   <<<dim3(Mq/128, 2*Hq/128), 256, SMEM_TOTAL>>>(bin);
    scan_chunks<<<dim3(Hq/256, NCHUNK, Bq), 256>>>();
    scan_tops  <<<16, 256>>>();
    scan_apply <<<dim3(Hq/256, NCHUNK, Bq), 256>>>();
    gemm2_tc   <<<dim3(Mq/128, Dq/128), 256, SMEM_TOTAL>>>(bout, out);
}

// round 9
// speedup vs baseline: 2.0581x; 1.0075x over previous
#include <cuda_runtime.h>
#include <cuda_bf16.h>
#include <cstdint>

// Problem constants
#define Bq 4
#define Lq 8192
#define Dq 512
#define Hq 1024
#define Mq (Bq*Lq)        // 32768
#define NCHUNK 128
#define CLEN 64

// ---------------------------------------------------------------------------
// Scratch (device globals; allocation is forbidden)
// ---------------------------------------------------------------------------
__device__ float g_c [Bq*Lq*Hq];
__device__ float g_zg[Bq*Lq*Hq];
__device__ float g_A [Bq*NCHUNK*Hq];
__device__ float g_Bc[Bq*NCHUNK*Hq];
__device__ float g_hs[Bq*NCHUNK*Hq];
__device__ __nv_bfloat16 g_xh[(size_t)Mq*Dq], g_xl[(size_t)Mq*Dq];
__device__ __nv_bfloat16 g_wih[2*Hq*Dq],      g_wil[2*Hq*Dq];
__device__ __nv_bfloat16 g_woh[Dq*Hq],        g_wol[Dq*Hq];
__device__ __nv_bfloat16 g_hh[(size_t)Mq*Hq], g_hl[(size_t)Mq*Hq];

// ---------------------------------------------------------------------------
// PTX helpers
// ---------------------------------------------------------------------------
__device__ __forceinline__ uint32_t s2u(const void* p) {
    uint32_t a;
    asm("{ .reg .u64 t; cvta.to.shared.u64 t, %1; cvt.u32.u64 %0, t; }"
        : "=r"(a) : "l"(p));
    return a;
}
#define LDSM_X4(r0,r1,r2,r3,addr) \
    asm volatile("ldmatrix.sync.aligned.m8n8.x4.shared.b16 {%0,%1,%2,%3}, [%4];" \
        : "=r"(r0),"=r"(r1),"=r"(r2),"=r"(r3) : "r"(addr))

#define MMA_BF16(c0,c1,c2,c3,a0,a1,a2,a3,b0,b1) \
    asm volatile("mma.sync.aligned.m16n8k16.row.col.f32.bf16.bf16.f32 " \
        "{%0,%1,%2,%3},{%4,%5,%6,%7},{%8,%9},{%0,%1,%2,%3};" \
        : "+f"(c0),"+f"(c1),"+f"(c2),"+f"(c3) \
        : "r"(a0),"r"(a1),"r"(a2),"r"(a3),"r"(b0),"r"(b1))

__device__ __forceinline__ void cpa16(uint32_t dst, const void* src) {
    asm volatile("cp.async.cg.shared.global [%0], [%1], 16;"
                 :: "r"(dst), "l"(src));
}
#define CP_COMMIT() asm volatile("cp.async.commit_group;")
#define CP_WAIT1()  asm volatile("cp.async.wait_group 1;")
#define CP_WAIT0()  asm volatile("cp.async.wait_group 0;")

// smem layout per stage: Ah(256xLDK) Al Bh(128xLDK) Bl
#define LDK 72
#define TILE_A (256*LDK*2)    // 36864
#define TILE_Bb (128*LDK*2)   // 18432
#define OFF_AL TILE_A
#define OFF_BH (2*TILE_A)
#define OFF_BL (2*TILE_A + TILE_Bb)
#define STAGE_B (2*TILE_A + 2*TILE_Bb)   // 110592
#define STAGES 2
#define SMEM_TOTAL (STAGES*STAGE_B)      // 221184

// ---------------------------------------------------------------------------
// split: f32 -> (hi, lo) bf16
// ---------------------------------------------------------------------------
__device__ __forceinline__ unsigned short bfu(__nv_bfloat16 h) {
    return *reinterpret_cast<unsigned short*>(&h);
}
__global__ void split_f32(const float* __restrict__ s,
                          __nv_bfloat16* __restrict__ hi,
                          __nv_bfloat16* __restrict__ lo, int n4)
{
    int i = blockIdx.x * blockDim.x + threadIdx.x;
    if (i >= n4) return;
    float4 v = ((const float4*)s)[i];
    __nv_bfloat16 hx = __float2bfloat16_rn(v.x);
    __nv_bfloat16 hy = __float2bfloat16_rn(v.y);
    __nv_bfloat16 hz = __float2bfloat16_rn(v.z);
    __nv_bfloat16 hw = __float2bfloat16_rn(v.w);
    uint2 H, L;
    H.x = (unsigned)bfu(hx) | ((unsigned)bfu(hy) << 16);
    H.y = (unsigned)bfu(hz) | ((unsigned)bfu(hw) << 16);
    __nv_bfloat16 lx = __float2bfloat16_rn(v.x - __bfloat162float(hx));
    __nv_bfloat16 ly = __float2bfloat16_rn(v.y - __bfloat162float(hy));
    __nv_bfloat16 lz = __float2bfloat16_rn(v.z - __bfloat162float(hz));
    __nv_bfloat16 lw = __float2bfloat16_rn(v.w - __bfloat162float(hw));
    L.x = (unsigned)bfu(lx) | ((unsigned)bfu(ly) << 16);
    L.y = (unsigned)bfu(lz) | ((unsigned)bfu(lw) << 16);
    ((uint2*)hi)[i] = H;
    ((uint2*)lo)[i] = L;
}

// ---------------------------------------------------------------------------
// MMA consume for one BK=64 stage. Warp tile 64x64 (4 m-frags x 8 n-frags).
// ---------------------------------------------------------------------------
__device__ __forceinline__ void mma_stage(uint32_t bb, int lane, int wm, int wn,
                                          float acc[4][8][4])
{
    #pragma unroll
    for (int ks = 0; ks < 4; ks++) {
        int kk = ks * 16;
        unsigned aH[4][4], aL[4][4];
        {
            int ar = lane & 15;
            int ac = kk + 8 * (lane >> 4);
            #pragma unroll
            for (int mi = 0; mi < 4; mi++) {
                unsigned off = ((wm + mi*16 + ar) * LDK + ac) * 2;
                LDSM_X4(aH[mi][0],aH[mi][1],aH[mi][2],aH[mi][3], bb + off);
                LDSM_X4(aL[mi][0],aL[mi][1],aL[mi][2],aL[mi][3], bb + OFF_AL + off);
            }
        }
        unsigned bH[8][2], bL[8][2];
        {
            int r  = lane & 7;
            int kc = kk + ((lane >> 3) & 1) * 8;
            int n8 = (lane >> 4) ? 8 : 0;
            #pragma unroll
            for (int p = 0; p < 4; p++) {
                unsigned off = ((wn + p*16 + n8 + r) * LDK + kc) * 2;
                LDSM_X4(bH[2*p][0],bH[2*p][1],bH[2*p+1][0],bH[2*p+1][1],
                        bb + OFF_BH + off);
                LDSM_X4(bL[2*p][0],bL[2*p][1],bL[2*p+1][0],bL[2*p+1][1],
                        bb + OFF_BL + off);
            }
        }
        #pragma unroll
        for (int mi = 0; mi < 4; mi++)
            #pragma unroll
            for (int ni = 0; ni < 8; ni++) {
                float* c = acc[mi][ni];
                MMA_BF16(c[0],c[1],c[2],c[3],
                         aH[mi][0],aH[mi][1],aH[mi][2],aH[mi][3],
                         bH[ni][0],bH[ni][1]);
                MMA_BF16(c[0],c[1],c[2],c[3],
                         aH[mi][0],aH[mi][1],aH[mi][2],aH[mi][3],
                         bL[ni][0],bL[ni][1]);
                MMA_BF16(c[0],c[1],c[2],c[3],
                         aL[mi][0],aL[mi][1],aL[mi][2],aL[mi][3],
                         bH[ni][0],bH[ni][1]);
            }
    }
}

// ---------------------------------------------------------------------------
// K1: gemm1 (x @ W_in^T) + activation epilogue. Block 256m x 128col, K=512.
// Col j -> channel ch0+(j>>1); j&1: 0=hidden W row, 1=gate W row.
// ---------------------------------------------------------------------------
__global__ __launch_bounds__(256)
void gemm1_tc(const float* __restrict__ bin)
{
    extern __shared__ char smem[];
    uint32_t su = s2u(smem);
    const int tid = threadIdx.x;
    const int lane = tid & 31;
    const int warp = tid >> 5;
    const int wm = (warp >> 1) * 64;      // 4 warps in m
    const int wn = (warp & 1) * 64;       // 2 warps in n
    const int m0 = blockIdx.x * 256;
    const int ch0 = blockIdx.y * 64;
    const int NC = Dq / 64;   // 8

    float acc[4][8][4];
    #pragma unroll
    for (int i = 0; i < 4; i++)
        #pragma unroll
        for (int j = 0; j < 8; j++)
            #pragma unroll
            for (int q = 0; q < 4; q++) acc[i][j][q] = 0.f;

    auto stage = [&](int c) {
        uint32_t bb = su + (c & 1) * STAGE_B;
        int k0 = c * 64;
        // A: 256 rows x 64 cols (hi + lo)
        #pragma unroll
        for (int i = 0; i < 8; i++) {
            int id = tid + 256 * i;
            int row = id >> 3, c16 = id & 7;
            uint32_t off = (uint32_t)(row * (LDK*2) + c16 * 16);
            size_t ai = (size_t)(m0 + row) * Dq + k0 + c16 * 8;
            cpa16(bb + off,          g_xh + ai);
            cpa16(bb + OFF_AL + off, g_xl + ai);
        }
        // B: 128 rows (interleaved hidden/gate) x 64 cols (hi + lo)
        #pragma unroll
        for (int i = 0; i < 4; i++) {
            int id = tid + 256 * i;
            int row = id >> 3, c16 = id & 7;
            uint32_t off = (uint32_t)(row * (LDK*2) + c16 * 16);
            int wrow = (row & 1) ? (Hq + ch0 + (row >> 1)) : (ch0 + (row >> 1));
            size_t bi = (size_t)wrow * Dq + k0 + c16 * 8;
            cpa16(bb + OFF_BH + off, g_wih + bi);
            cpa16(bb + OFF_BL + off, g_wil + bi);
        }
        CP_COMMIT();
    };

    stage(0); stage(1);
    for (int c = 0; c < NC; c++) {
        if (c + 1 < NC) { CP_WAIT1(); } else { CP_WAIT0(); }
        __syncthreads();
        mma_stage(su + (c & 1) * STAGE_B, lane, wm, wn, acc);
        __syncthreads();
        if (c + 2 < NC) stage(c + 2);
    }

    // epilogue: activations
    #pragma unroll
    for (int ni = 0; ni < 8; ni++) {
        int nloc = wn + ni*8 + 2*(lane & 3);
        int ch = ch0 + (nloc >> 1);
        float bh = bin[ch], bg = bin[Hq + ch];
        #pragma unroll
        for (int mi = 0; mi < 4; mi++) {
            float* c = acc[mi][ni];
            #pragma unroll
            for (int half = 0; half < 2; half++) {
                int row = m0 + wm + mi*16 + (lane >> 2) + half*8;
                float hid = c[2*half]   + bh;
                float gat = c[2*half+1] + bg;
                float z  = 1.f/(1.f + __expf(-gat));
                float cc = 1.f - z;
                float gt = (hid >= 0.f) ? (hid + 0.5f)
                                        : (1.f/(1.f + __expf(-hid)));
                g_c [(size_t)row*Hq + ch] = cc;
                g_zg[(size_t)row*Hq + ch] = z * gt;
            }
        }
    }
}

// ---------------------------------------------------------------------------
// K2-K4: chunked scan
// ---------------------------------------------------------------------------
__global__ void scan_chunks()
{
    int h = blockIdx.x*256 + threadIdx.x;
    int chunk = blockIdx.y, b = blockIdx.z;
    size_t base = ((size_t)b*Lq + (size_t)chunk*CLEN)*Hq + h;
    float A = 1.f, Bv = 0.f;
    #pragma unroll 8
    for (int t = 0; t < CLEN; t++) {
        float c = g_c[base], z = g_zg[base];
        Bv = c*Bv + z;
        A *= c;
        base += Hq;
    }
    size_t o = ((size_t)b*NCHUNK + chunk)*Hq + h;
    g_A[o] = A; g_Bc[o] = Bv;
}

__global__ void scan_tops()
{
    int g = blockIdx.x*256 + threadIdx.x;
    int b = g >> 10, hh = g & 1023;
    float hs = 0.f;
    size_t o = ((size_t)b*NCHUNK)*Hq + hh;
    for (int i = 0; i < NCHUNK; i++) {
        g_hs[o] = hs;
        hs = g_A[o]*hs + g_Bc[o];
        o += Hq;
    }
}

__global__ void scan_apply()
{
    int h = blockIdx.x*256 + threadIdx.x;
    int chunk = blockIdx.y, b = blockIdx.z;
    float hs = g_hs[((size_t)b*NCHUNK + chunk)*Hq + h];
    size_t base = ((size_t)b*Lq + (size_t)chunk*CLEN)*Hq + h;
    #pragma unroll 8
    for (int t = 0; t < CLEN; t++) {
        float c = g_c[base], z = g_zg[base];
        hs = c*hs + z;
        __nv_bfloat16 hi = __float2bfloat16_rn(hs);
        g_hh[base] = hi;
        g_hl[base] = __float2bfloat16_rn(hs - __bfloat162float(hi));
        base += Hq;
    }
}

// ---------------------------------------------------------------------------
// K5: gemm2 (h @ W_out^T + b_out). Block 256m x 128n, K=1024.
// ---------------------------------------------------------------------------
__global__ __launch_bounds__(256)
void gemm2_tc(const float* __restrict__ bout, float* __restrict__ Out)
{
    extern __shared__ char smem[];
    uint32_t su = s2u(smem);
    const int tid = threadIdx.x;
    const int lane = tid & 31;
    const int warp = tid >> 5;
    const int wm = (warp >> 1) * 64;
    const int wn = (warp & 1) * 64;
    const int m0 = blockIdx.x * 256;
    const int n0 = blockIdx.y * 128;
    const int NC = Hq / 64;   // 16

    float acc[4][8][4];
    #pragma unroll
    for (int i = 0; i < 4; i++)
        #pragma unroll
        for (int j = 0; j < 8; j++)
            #pragma unroll
            for (int q = 0; q < 4; q++) acc[i][j][q] = 0.f;

    auto stage = [&](int c) {
        uint32_t bb = su + (c & 1) * STAGE_B;
        int k0 = c * 64;
        #pragma unroll
        for (int i = 0; i < 8; i++) {
            int id = tid + 256 * i;
            int row = id >> 3, c16 = id & 7;
            uint32_t off = (uint32_t)(row * (LDK*2) + c16 * 16);
            size_t ai = (size_t)(m0 + row) * Hq + k0 + c16 * 8;
            cpa16(bb + off,          g_hh + ai);
            cpa16(bb + OFF_AL + off, g_hl + ai);
        }
        #pragma unroll
        for (int i = 0; i < 4; i++) {
            int id = tid + 256 * i;
            int row = id >> 3, c16 = id & 7;
            uint32_t off = (uint32_t)(row * (LDK*2) + c16 * 16);
            size_t bi = (size_t)(n0 + row) * Hq + k0 + c16 * 8;
            cpa16(bb + OFF_BH + off, g_woh + bi);
            cpa16(bb + OFF_BL + off, g_wol + bi);
        }
        CP_COMMIT();
    };

    stage(0); stage(1);
    for (int c = 0; c < NC; c++) {
        if (c + 1 < NC) { CP_WAIT1(); } else { CP_WAIT0(); }
        __syncthreads();
        mma_stage(su + (c & 1) * STAGE_B, lane, wm, wn, acc);
        __syncthreads();
        if (c + 2 < NC) stage(c + 2);
    }

    #pragma unroll
    for (int ni = 0; ni < 8; ni++) {
        int nd = n0 + wn + ni*8 + 2*(lane & 3);
        float b0 = bout[nd], b1 = bout[nd+1];
        #pragma unroll
        for (int mi = 0; mi < 4; mi++) {
            float* c = acc[mi][ni];
            #pragma unroll
            for (int half = 0; half < 2; half++) {
                int row = m0 + wm + mi*16 + (lane >> 2) + half*8;
                float2 o;
                o.x = c[2*half]   + b0;
                o.y = c[2*half+1] + b1;
                *(float2*)(Out + (size_t)row*Dq + nd) = o;
            }
        }
    }
}

// ---------------------------------------------------------------------------
extern "C" void kernel_launch(void* const* d_in, const int* in_sizes, int n_in,
                              void* d_out, int out_size)
{
    const float *x = nullptr, *win = nullptr, *bin = nullptr,
                *wout = nullptr, *bout = nullptr;
    for (int i = 0; i < n_in; i++) {
        switch (in_sizes[i]) {
            case Bq*Lq*Dq: x    = (const float*)d_in[i]; break;
            case 2*Hq*Dq:  win  = (const float*)d_in[i]; break;
            case 2*Hq:     bin  = (const float*)d_in[i]; break;
            case Dq*Hq:    wout = (const float*)d_in[i]; break;
            case Dq:       bout = (const float*)d_in[i]; break;
        }
    }
    float* out = (float*)d_out;

    static bool attr_done = false;
    if (!attr_done) {
        cudaFuncSetAttribute(gemm1_tc, cudaFuncAttributeMaxDynamicSharedMemorySize, SMEM_TOTAL);
        cudaFuncSetAttribute(gemm2_tc, cudaFuncAttributeMaxDynamicSharedMemorySize, SMEM_TOTAL);
        attr_done = true;
    }

    __nv_bfloat16 *xh, *xl, *wih, *wil, *woh, *wol;
    cudaGetSymbolAddress((void**)&xh,  g_xh);
    cudaGetSymbolAddress((void**)&xl,  g_xl);
    cudaGetSymbolAddress((void**)&wih, g_wih);
    cudaGetSymbolAddress((void**)&wil, g_wil);
    cudaGetSymbolAddress((void**)&woh, g_woh);
    cudaGetSymbolAddress((void**)&wol, g_wol);

    split_f32<<<(Mq*Dq/4 + 255)/256, 256>>>(x, xh, xl, Mq*Dq/4);
    split_f32<<<(2*Hq*Dq/4 + 255)/256, 256>>>(win, wih, wil, 2*Hq*Dq/4);
    split_f32<<<(Dq*Hq/4 + 255)/256, 256>>>(wout, woh, wol, Dq*Hq/4);

    gemm1_tc   <<<dim3(Mq/256, 2*Hq/128), 256, SMEM_TOTAL>>>(bin);
    scan_chunks<<<dim3(Hq/256, NCHUNK, Bq), 256>>>();
    scan_tops  <<<16, 256>>>();
    scan_apply <<<dim3(Hq/256, NCHUNK, Bq), 256>>>();
    gemm2_tc   <<<dim3(Mq/256, Dq/128), 256, SMEM_TOTAL>>>(bout, out);
}

// round 10
// speedup vs baseline: 2.3247x; 1.1296x over previous
#include <cuda_runtime.h>
#include <cuda_bf16.h>
#include <cstdint>

// Problem constants
#define Bq 4
#define Lq 8192
#define Dq 512
#define Hq 1024
#define Mq (Bq*Lq)        // 32768
#define NCHUNK 128
#define CLEN 64

// ---------------------------------------------------------------------------
// Scratch (device globals; allocation is forbidden)
// ---------------------------------------------------------------------------
__device__ float g_c [Bq*Lq*Hq];
__device__ float g_zg[Bq*Lq*Hq];
__device__ float g_A [Bq*NCHUNK*Hq];
__device__ float g_Bc[Bq*NCHUNK*Hq];
__device__ float g_hs[Bq*NCHUNK*Hq];
__device__ __nv_bfloat16 g_xh[(size_t)Mq*Dq], g_xl[(size_t)Mq*Dq];
__device__ __nv_bfloat16 g_wih[2*Hq*Dq],      g_wil[2*Hq*Dq];
__device__ __nv_bfloat16 g_woh[Dq*Hq],        g_wol[Dq*Hq];
__device__ __nv_bfloat16 g_hh[(size_t)Mq*Hq], g_hl[(size_t)Mq*Hq];

// ---------------------------------------------------------------------------
// PTX helpers
// ---------------------------------------------------------------------------
__device__ __forceinline__ uint32_t s2u(const void* p) {
    uint32_t a;
    asm("{ .reg .u64 t; cvta.to.shared.u64 t, %1; cvt.u32.u64 %0, t; }"
        : "=r"(a) : "l"(p));
    return a;
}
#define LDSM_X4(r0,r1,r2,r3,addr) \
    asm volatile("ldmatrix.sync.aligned.m8n8.x4.shared.b16 {%0,%1,%2,%3}, [%4];" \
        : "=r"(r0),"=r"(r1),"=r"(r2),"=r"(r3) : "r"(addr))

#define MMA_BF16(c0,c1,c2,c3,a0,a1,a2,a3,b0,b1) \
    asm volatile("mma.sync.aligned.m16n8k16.row.col.f32.bf16.bf16.f32 " \
        "{%0,%1,%2,%3},{%4,%5,%6,%7},{%8,%9},{%0,%1,%2,%3};" \
        : "+f"(c0),"+f"(c1),"+f"(c2),"+f"(c3) \
        : "r"(a0),"r"(a1),"r"(a2),"r"(a3),"r"(b0),"r"(b1))

__device__ __forceinline__ void cpa16(uint32_t dst, const void* src) {
    asm volatile("cp.async.cg.shared.global [%0], [%1], 16;"
                 :: "r"(dst), "l"(src));
}
#define CP_COMMIT() asm volatile("cp.async.commit_group;")
#define CP_WAIT1()  asm volatile("cp.async.wait_group 1;")
#define CP_WAIT0()  asm volatile("cp.async.wait_group 0;")

// smem: BK=32, LDK=40 (80B rows — conflict-free ldmatrix: stride cycles all banks)
#define LDK 40
#define TILE128 (128*LDK*2)            // 10240 bytes per 128-row tile
#define OFF_AH 0
#define OFF_AL TILE128
#define OFF_BH (2*TILE128)
#define OFF_BL (3*TILE128)
#define STAGE_B (4*TILE128)            // 40960
#define SMEM_TOTAL (2*STAGE_B)         // 81920 -> 2 CTAs/SM

// ---------------------------------------------------------------------------
// split: f32 -> (hi, lo) bf16
// ---------------------------------------------------------------------------
__device__ __forceinline__ unsigned short bfu(__nv_bfloat16 h) {
    return *reinterpret_cast<unsigned short*>(&h);
}
__global__ void split_f32(const float* __restrict__ s,
                          __nv_bfloat16* __restrict__ hi,
                          __nv_bfloat16* __restrict__ lo, int n4)
{
    int i = blockIdx.x * blockDim.x + threadIdx.x;
    if (i >= n4) return;
    float4 v = ((const float4*)s)[i];
    __nv_bfloat16 hx = __float2bfloat16_rn(v.x);
    __nv_bfloat16 hy = __float2bfloat16_rn(v.y);
    __nv_bfloat16 hz = __float2bfloat16_rn(v.z);
    __nv_bfloat16 hw = __float2bfloat16_rn(v.w);
    uint2 H, L;
    H.x = (unsigned)bfu(hx) | ((unsigned)bfu(hy) << 16);
    H.y = (unsigned)bfu(hz) | ((unsigned)bfu(hw) << 16);
    __nv_bfloat16 lx = __float2bfloat16_rn(v.x - __bfloat162float(hx));
    __nv_bfloat16 ly = __float2bfloat16_rn(v.y - __bfloat162float(hy));
    __nv_bfloat16 lz = __float2bfloat16_rn(v.z - __bfloat162float(hz));
    __nv_bfloat16 lw = __float2bfloat16_rn(v.w - __bfloat162float(hw));
    L.x = (unsigned)bfu(lx) | ((unsigned)bfu(ly) << 16);
    L.y = (unsigned)bfu(lz) | ((unsigned)bfu(lw) << 16);
    ((uint2*)hi)[i] = H;
    ((uint2*)lo)[i] = L;
}

// ---------------------------------------------------------------------------
// MMA consume for one BK=32 stage. Warp tile 64m x 32n (4 m-frags x 4 n-frags).
// ---------------------------------------------------------------------------
__device__ __forceinline__ void mma_stage(uint32_t bb, int lane, int wm, int wn,
                                          float acc[4][4][4])
{
    #pragma unroll
    for (int ks = 0; ks < 2; ks++) {
        int kk = ks * 16;
        unsigned aH[4][4], aL[4][4];
        {
            int ar = lane & 15;
            int ac = kk + 8 * (lane >> 4);
            #pragma unroll
            for (int mi = 0; mi < 4; mi++) {
                unsigned off = ((wm + mi*16 + ar) * LDK + ac) * 2;
                LDSM_X4(aH[mi][0],aH[mi][1],aH[mi][2],aH[mi][3], bb + OFF_AH + off);
                LDSM_X4(aL[mi][0],aL[mi][1],aL[mi][2],aL[mi][3], bb + OFF_AL + off);
            }
        }
        unsigned bH[4][2], bL[4][2];
        {
            int r  = lane & 7;
            int kc = kk + ((lane >> 3) & 1) * 8;
            int n8 = (lane >> 4) ? 8 : 0;
            #pragma unroll
            for (int p = 0; p < 2; p++) {
                unsigned off = ((wn + p*16 + n8 + r) * LDK + kc) * 2;
                LDSM_X4(bH[2*p][0],bH[2*p][1],bH[2*p+1][0],bH[2*p+1][1],
                        bb + OFF_BH + off);
                LDSM_X4(bL[2*p][0],bL[2*p][1],bL[2*p+1][0],bL[2*p+1][1],
                        bb + OFF_BL + off);
            }
        }
        #pragma unroll
        for (int mi = 0; mi < 4; mi++)
            #pragma unroll
            for (int ni = 0; ni < 4; ni++) {
                float* c = acc[mi][ni];
                MMA_BF16(c[0],c[1],c[2],c[3],
                         aH[mi][0],aH[mi][1],aH[mi][2],aH[mi][3],
                         bH[ni][0],bH[ni][1]);
                MMA_BF16(c[0],c[1],c[2],c[3],
                         aH[mi][0],aH[mi][1],aH[mi][2],aH[mi][3],
                         bL[ni][0],bL[ni][1]);
                MMA_BF16(c[0],c[1],c[2],c[3],
                         aL[mi][0],aL[mi][1],aL[mi][2],aL[mi][3],
                         bH[ni][0],bH[ni][1]);
            }
    }
}

// ---------------------------------------------------------------------------
// K1: gemm1 (x @ W_in^T) + activation epilogue. Block 128m x 128col, K=512.
// Col j -> channel ch0+(j>>1); j&1: 0=hidden W row, 1=gate W row.
// Warps: 2 m-groups x 4 n-groups, warp tile 64x32.
// ---------------------------------------------------------------------------
__global__ __launch_bounds__(256, 2)
void gemm1_tc(const float* __restrict__ bin)
{
    extern __shared__ char smem[];
    uint32_t su = s2u(smem);
    const int tid = threadIdx.x;
    const int lane = tid & 31;
    const int warp = tid >> 5;
    const int wm = (warp >> 2) * 64;
    const int wn = (warp & 3) * 32;
    const int m0 = blockIdx.x * 128;
    const int ch0 = blockIdx.y * 64;
    const int NC = Dq / 32;   // 16

    float acc[4][4][4];
    #pragma unroll
    for (int i = 0; i < 4; i++)
        #pragma unroll
        for (int j = 0; j < 4; j++)
            #pragma unroll
            for (int q = 0; q < 4; q++) acc[i][j][q] = 0.f;

    auto stage = [&](int c) {
        uint32_t bb = su + (c & 1) * STAGE_B;
        int k0 = c * 32;
        #pragma unroll
        for (int i = 0; i < 2; i++) {
            int id = tid + 256 * i;
            int row = id >> 2, c8 = id & 3;
            uint32_t off = (uint32_t)(row * (LDK*2) + c8 * 16);
            size_t ai = (size_t)(m0 + row) * Dq + k0 + c8 * 8;
            cpa16(bb + OFF_AH + off, g_xh + ai);
            cpa16(bb + OFF_AL + off, g_xl + ai);
            int wrow = (row & 1) ? (Hq + ch0 + (row >> 1)) : (ch0 + (row >> 1));
            size_t bi = (size_t)wrow * Dq + k0 + c8 * 8;
            cpa16(bb + OFF_BH + off, g_wih + bi);
            cpa16(bb + OFF_BL + off, g_wil + bi);
        }
        CP_COMMIT();
    };

    stage(0); stage(1);
    for (int c = 0; c < NC; c++) {
        if (c + 1 < NC) { CP_WAIT1(); } else { CP_WAIT0(); }
        __syncthreads();
        mma_stage(su + (c & 1) * STAGE_B, lane, wm, wn, acc);
        __syncthreads();
        if (c + 2 < NC) stage(c + 2);
    }

    // epilogue: activations
    #pragma unroll
    for (int ni = 0; ni < 4; ni++) {
        int nloc = wn + ni*8 + 2*(lane & 3);
        int ch = ch0 + (nloc >> 1);
        float bh = bin[ch], bg = bin[Hq + ch];
        #pragma unroll
        for (int mi = 0; mi < 4; mi++) {
            float* c = acc[mi][ni];
            #pragma unroll
            for (int half = 0; half < 2; half++) {
                int row = m0 + wm + mi*16 + (lane >> 2) + half*8;
                float hid = c[2*half]   + bh;
                float gat = c[2*half+1] + bg;
                float z  = 1.f/(1.f + __expf(-gat));
                float cc = 1.f - z;
                float gt = (hid >= 0.f) ? (hid + 0.5f)
                                        : (1.f/(1.f + __expf(-hid)));
                g_c [(size_t)row*Hq + ch] = cc;
                g_zg[(size_t)row*Hq + ch] = z * gt;
            }
        }
    }
}

// ---------------------------------------------------------------------------
// K2-K4: chunked scan
// ---------------------------------------------------------------------------
__global__ void scan_chunks()
{
    int h = blockIdx.x*256 + threadIdx.x;
    int chunk = blockIdx.y, b = blockIdx.z;
    size_t base = ((size_t)b*Lq + (size_t)chunk*CLEN)*Hq + h;
    float A = 1.f, Bv = 0.f;
    #pragma unroll 8
    for (int t = 0; t < CLEN; t++) {
        float c = g_c[base], z = g_zg[base];
        Bv = c*Bv + z;
        A *= c;
        base += Hq;
    }
    size_t o = ((size_t)b*NCHUNK + chunk)*Hq + h;
    g_A[o] = A; g_Bc[o] = Bv;
}

__global__ void scan_tops()
{
    int g = blockIdx.x*256 + threadIdx.x;
    int b = g >> 10, hh = g & 1023;
    float hs = 0.f;
    size_t o = ((size_t)b*NCHUNK)*Hq + hh;
    for (int i = 0; i < NCHUNK; i++) {
        g_hs[o] = hs;
        hs = g_A[o]*hs + g_Bc[o];
        o += Hq;
    }
}

__global__ void scan_apply()
{
    int h = blockIdx.x*256 + threadIdx.x;
    int chunk = blockIdx.y, b = blockIdx.z;
    float hs = g_hs[((size_t)b*NCHUNK + chunk)*Hq + h];
    size_t base = ((size_t)b*Lq + (size_t)chunk*CLEN)*Hq + h;
    #pragma unroll 8
    for (int t = 0; t < CLEN; t++) {
        float c = g_c[base], z = g_zg[base];
        hs = c*hs + z;
        __nv_bfloat16 hi = __float2bfloat16_rn(hs);
        g_hh[base] = hi;
        g_hl[base] = __float2bfloat16_rn(hs - __bfloat162float(hi));
        base += Hq;
    }
}

// ---------------------------------------------------------------------------
// K5: gemm2 (h @ W_out^T + b_out). Block 128m x 128n, K=1024.
// ---------------------------------------------------------------------------
__global__ __launch_bounds__(256, 2)
void gemm2_tc(const float* __restrict__ bout, float* __restrict__ Out)
{
    extern __shared__ char smem[];
    uint32_t su = s2u(smem);
    const int tid = threadIdx.x;
    const int lane = tid & 31;
    const int warp = tid >> 5;
    const int wm = (warp >> 2) * 64;
    const int wn = (warp & 3) * 32;
    const int m0 = blockIdx.x * 128;
    const int n0 = blockIdx.y * 128;
    const int NC = Hq / 32;   // 32

    float acc[4][4][4];
    #pragma unroll
    for (int i = 0; i < 4; i++)
        #pragma unroll
        for (int j = 0; j < 4; j++)
            #pragma unroll
            for (int q = 0; q < 4; q++) acc[i][j][q] = 0.f;

    auto stage = [&](int c) {
        uint32_t bb = su + (c & 1) * STAGE_B;
        int k0 = c * 32;
        #pragma unroll
        for (int i = 0; i < 2; i++) {
            int id = tid + 256 * i;
            int row = id >> 2, c8 = id & 3;
            uint32_t off = (uint32_t)(row * (LDK*2) + c8 * 16);
            size_t ai = (size_t)(m0 + row) * Hq + k0 + c8 * 8;
            cpa16(bb + OFF_AH + off, g_hh + ai);
            cpa16(bb + OFF_AL + off, g_hl + ai);
            size_t bi = (size_t)(n0 + row) * Hq + k0 + c8 * 8;
            cpa16(bb + OFF_BH + off, g_woh + bi);
            cpa16(bb + OFF_BL + off, g_wol + bi);
        }
        CP_COMMIT();
    };

    stage(0); stage(1);
    for (int c = 0; c < NC; c++) {
        if (c + 1 < NC) { CP_WAIT1(); } else { CP_WAIT0(); }
        __syncthreads();
        mma_stage(su + (c & 1) * STAGE_B, lane, wm, wn, acc);
        __syncthreads();
        if (c + 2 < NC) stage(c + 2);
    }

    #pragma unroll
    for (int ni = 0; ni < 4; ni++) {
        int nd = n0 + wn + ni*8 + 2*(lane & 3);
        float b0 = bout[nd], b1 = bout[nd+1];
        #pragma unroll
        for (int mi = 0; mi < 4; mi++) {
            float* c = acc[mi][ni];
            #pragma unroll
            for (int half = 0; half < 2; half++) {
                int row = m0 + wm + mi*16 + (lane >> 2) + half*8;
                float2 o;
                o.x = c[2*half]   + b0;
                o.y = c[2*half+1] + b1;
                *(float2*)(Out + (size_t)row*Dq + nd) = o;
            }
        }
    }
}

// ---------------------------------------------------------------------------
extern "C" void kernel_launch(void* const* d_in, const int* in_sizes, int n_in,
                              void* d_out, int out_size)
{
    const float *x = nullptr, *win = nullptr, *bin = nullptr,
                *wout = nullptr, *bout = nullptr;
    for (int i = 0; i < n_in; i++) {
        switch (in_sizes[i]) {
            case Bq*Lq*Dq: x    = (const float*)d_in[i]; break;
            case 2*Hq*Dq:  win  = (const float*)d_in[i]; break;
            case 2*Hq:     bin  = (const float*)d_in[i]; break;
            case Dq*Hq:    wout = (const float*)d_in[i]; break;
            case Dq:       bout = (const float*)d_in[i]; break;
        }
    }
    float* out = (float*)d_out;

    static bool attr_done = false;
    if (!attr_done) {
        cudaFuncSetAttribute(gemm1_tc, cudaFuncAttributeMaxDynamicSharedMemorySize, SMEM_TOTAL);
        cudaFuncSetAttribute(gemm2_tc, cudaFuncAttributeMaxDynamicSharedMemorySize, SMEM_TOTAL);
        attr_done = true;
    }

    __nv_bfloat16 *xh, *xl, *wih, *wil, *woh, *wol;
    cudaGetSymbolAddress((void**)&xh,  g_xh);
    cudaGetSymbolAddress((void**)&xl,  g_xl);
    cudaGetSymbolAddress((void**)&wih, g_wih);
    cudaGetSymbolAddress((void**)&wil, g_wil);
    cudaGetSymbolAddress((void**)&woh, g_woh);
    cudaGetSymbolAddress((void**)&wol, g_wol);

    split_f32<<<(Mq*Dq/4 + 255)/256, 256>>>(x, xh, xl, Mq*Dq/4);
    split_f32<<<(2*Hq*Dq/4 + 255)/256, 256>>>(win, wih, wil, 2*Hq*Dq/4);
    split_f32<<<(Dq*Hq/4 + 255)/256, 256>>>(wout, woh, wol, Dq*Hq/4);

    gemm1_tc   <<<dim3(Mq/128, 2*Hq/128), 256, SMEM_TOTAL>>>(bin);
    scan_chunks<<<dim3(Hq/256, NCHUNK, Bq), 256>>>();
    scan_tops  <<<16, 256>>>();
    scan_apply <<<dim3(Hq/256, NCHUNK, Bq), 256>>>();
    gemm2_tc   <<<dim3(Mq/128, Dq/128), 256, SMEM_TOTAL>>>(bout, out);
}

// round 11
// speedup vs baseline: 2.9710x; 1.2780x over previous
#include <cuda_runtime.h>
#include <cuda_fp16.h>
#include <cstdint>

// Problem constants
#define Bq 4
#define Lq 8192
#define Dq 512
#define Hq 1024
#define Mq (Bq*Lq)        // 32768
#define NCHUNK 128
#define CLEN 64

// ---------------------------------------------------------------------------
// Scratch (device globals; allocation is forbidden)
// ---------------------------------------------------------------------------
__device__ float g_c [Bq*Lq*Hq];
__device__ float g_zg[Bq*Lq*Hq];
__device__ float g_A [Bq*NCHUNK*Hq];
__device__ float g_Bc[Bq*NCHUNK*Hq];
__device__ float g_hs[Bq*NCHUNK*Hq];
__device__ __half g_xh[(size_t)Mq*Dq], g_xl[(size_t)Mq*Dq];
__device__ __half g_wih[2*Hq*Dq];
__device__ __half g_woh[Dq*Hq];
__device__ __half g_hh[(size_t)Mq*Hq], g_hl[(size_t)Mq*Hq];

// ---------------------------------------------------------------------------
// PTX helpers
// ---------------------------------------------------------------------------
__device__ __forceinline__ uint32_t s2u(const void* p) {
    uint32_t a;
    asm("{ .reg .u64 t; cvta.to.shared.u64 t, %1; cvt.u32.u64 %0, t; }"
        : "=r"(a) : "l"(p));
    return a;
}
#define LDSM_X4(r0,r1,r2,r3,addr) \
    asm volatile("ldmatrix.sync.aligned.m8n8.x4.shared.b16 {%0,%1,%2,%3}, [%4];" \
        : "=r"(r0),"=r"(r1),"=r"(r2),"=r"(r3) : "r"(addr))

#define MMA_F16(c0,c1,c2,c3,a0,a1,a2,a3,b0,b1) \
    asm volatile("mma.sync.aligned.m16n8k16.row.col.f32.f16.f16.f32 " \
        "{%0,%1,%2,%3},{%4,%5,%6,%7},{%8,%9},{%0,%1,%2,%3};" \
        : "+f"(c0),"+f"(c1),"+f"(c2),"+f"(c3) \
        : "r"(a0),"r"(a1),"r"(a2),"r"(a3),"r"(b0),"r"(b1))

__device__ __forceinline__ void cpa16(uint32_t dst, const void* src) {
    asm volatile("cp.async.cg.shared.global [%0], [%1], 16;"
                 :: "r"(dst), "l"(src));
}
#define CP_COMMIT() asm volatile("cp.async.commit_group;")
#define CP_WAIT1()  asm volatile("cp.async.wait_group 1;")
#define CP_WAIT0()  asm volatile("cp.async.wait_group 0;")

// smem: BK=32, LDK=40 (80B rows, conflict-free ldmatrix). 3 tiles/stage.
#define LDK 40
#define TILE128 (128*LDK*2)            // 10240
#define OFF_AH 0
#define OFF_AL TILE128
#define OFF_BH (2*TILE128)
#define STAGE_B (3*TILE128)            // 30720
#define SMEM_TOTAL (3*STAGE_B)         // 92160 -> 2 CTAs/SM

// ---------------------------------------------------------------------------
// split kernels: f32 -> fp16 hi (+ lo)
// ---------------------------------------------------------------------------
__device__ __forceinline__ unsigned short hfu(__half h) {
    return *reinterpret_cast<unsigned short*>(&h);
}
__global__ void split2_f16(const float* __restrict__ s,
                           __half* __restrict__ hi,
                           __half* __restrict__ lo, int n4)
{
    int i = blockIdx.x * blockDim.x + threadIdx.x;
    if (i >= n4) return;
    float4 v = ((const float4*)s)[i];
    __half hx = __float2half_rn(v.x), hy = __float2half_rn(v.y);
    __half hz = __float2half_rn(v.z), hw = __float2half_rn(v.w);
    uint2 H, L;
    H.x = (unsigned)hfu(hx) | ((unsigned)hfu(hy) << 16);
    H.y = (unsigned)hfu(hz) | ((unsigned)hfu(hw) << 16);
    __half lx = __float2half_rn(v.x - __half2float(hx));
    __half ly = __float2half_rn(v.y - __half2float(hy));
    __half lz = __float2half_rn(v.z - __half2float(hz));
    __half lw = __float2half_rn(v.w - __half2float(hw));
    L.x = (unsigned)hfu(lx) | ((unsigned)hfu(ly) << 16);
    L.y = (unsigned)hfu(lz) | ((unsigned)hfu(lw) << 16);
    ((uint2*)hi)[i] = H;
    ((uint2*)lo)[i] = L;
}
__global__ void conv_f16(const float* __restrict__ s,
                         __half* __restrict__ hi, int n4)
{
    int i = blockIdx.x * blockDim.x + threadIdx.x;
    if (i >= n4) return;
    float4 v = ((const float4*)s)[i];
    __half hx = __float2half_rn(v.x), hy = __float2half_rn(v.y);
    __half hz = __float2half_rn(v.z), hw = __float2half_rn(v.w);
    uint2 H;
    H.x = (unsigned)hfu(hx) | ((unsigned)hfu(hy) << 16);
    H.y = (unsigned)hfu(hz) | ((unsigned)hfu(hw) << 16);
    ((uint2*)hi)[i] = H;
}

// ---------------------------------------------------------------------------
// MMA consume for one BK=32 stage. Warp tile 32m x 64n (2 m-frags x 8 n-frags).
// 2 MMAs per tile: aH*bH + aL*bH.
// ---------------------------------------------------------------------------
__device__ __forceinline__ void mma_stage(uint32_t bb, int lane, int wm, int wn,
                                          float acc[2][8][4])
{
    #pragma unroll
    for (int ks = 0; ks < 2; ks++) {
        int kk = ks * 16;
        unsigned aH[2][4], aL[2][4];
        {
            int ar = lane & 15;
            int ac = kk + 8 * (lane >> 4);
            #pragma unroll
            for (int mi = 0; mi < 2; mi++) {
                unsigned off = ((wm + mi*16 + ar) * LDK + ac) * 2;
                LDSM_X4(aH[mi][0],aH[mi][1],aH[mi][2],aH[mi][3], bb + OFF_AH + off);
                LDSM_X4(aL[mi][0],aL[mi][1],aL[mi][2],aL[mi][3], bb + OFF_AL + off);
            }
        }
        unsigned bH[8][2];
        {
            int r  = lane & 7;
            int kc = kk + ((lane >> 3) & 1) * 8;
            int n8 = (lane >> 4) ? 8 : 0;
            #pragma unroll
            for (int p = 0; p < 4; p++) {
                unsigned off = ((wn + p*16 + n8 + r) * LDK + kc) * 2;
                LDSM_X4(bH[2*p][0],bH[2*p][1],bH[2*p+1][0],bH[2*p+1][1],
                        bb + OFF_BH + off);
            }
        }
        #pragma unroll
        for (int mi = 0; mi < 2; mi++)
            #pragma unroll
            for (int ni = 0; ni < 8; ni++) {
                float* c = acc[mi][ni];
                MMA_F16(c[0],c[1],c[2],c[3],
                        aH[mi][0],aH[mi][1],aH[mi][2],aH[mi][3],
                        bH[ni][0],bH[ni][1]);
                MMA_F16(c[0],c[1],c[2],c[3],
                        aL[mi][0],aL[mi][1],aL[mi][2],aL[mi][3],
                        bH[ni][0],bH[ni][1]);
            }
    }
}

// ---------------------------------------------------------------------------
// K1: gemm1 (x @ W_in^T) + activation epilogue. Block 128m x 128col, K=512.
// Col j -> channel ch0+(j>>1); j&1: 0=hidden W row, 1=gate W row.
// Warps: 4 m-groups x 2 n-groups, warp tile 32x64. 3-stage, 1 sync/iter.
// ---------------------------------------------------------------------------
__global__ __launch_bounds__(256, 2)
void gemm1_tc(const float* __restrict__ bin)
{
    extern __shared__ char smem[];
    uint32_t su = s2u(smem);
    const int tid = threadIdx.x;
    const int lane = tid & 31;
    const int warp = tid >> 5;
    const int wm = (warp >> 1) * 32;
    const int wn = (warp & 1) * 64;
    const int m0 = blockIdx.x * 128;
    const int ch0 = blockIdx.y * 64;
    const int NC = Dq / 32;   // 16

    float acc[2][8][4];
    #pragma unroll
    for (int i = 0; i < 2; i++)
        #pragma unroll
        for (int j = 0; j < 8; j++)
            #pragma unroll
            for (int q = 0; q < 4; q++) acc[i][j][q] = 0.f;

    auto stage = [&](int c) {
        uint32_t bb = su + (c % 3) * STAGE_B;
        int k0 = c * 32;
        #pragma unroll
        for (int i = 0; i < 2; i++) {
            int id = tid + 256 * i;
            int row = id >> 2, c8 = id & 3;
            uint32_t off = (uint32_t)(row * (LDK*2) + c8 * 16);
            size_t ai = (size_t)(m0 + row) * Dq + k0 + c8 * 8;
            cpa16(bb + OFF_AH + off, g_xh + ai);
            cpa16(bb + OFF_AL + off, g_xl + ai);
            int wrow = (row & 1) ? (Hq + ch0 + (row >> 1)) : (ch0 + (row >> 1));
            size_t bi = (size_t)wrow * Dq + k0 + c8 * 8;
            cpa16(bb + OFF_BH + off, g_wih + bi);
        }
        CP_COMMIT();
    };

    stage(0); stage(1);
    for (int c = 0; c < NC; c++) {
        if (c + 1 < NC) { CP_WAIT1(); } else { CP_WAIT0(); }
        __syncthreads();
        if (c + 2 < NC) stage(c + 2);
        mma_stage(su + (c % 3) * STAGE_B, lane, wm, wn, acc);
    }

    // epilogue: activations
    #pragma unroll
    for (int ni = 0; ni < 8; ni++) {
        int nloc = wn + ni*8 + 2*(lane & 3);
        int ch = ch0 + (nloc >> 1);
        float bh = bin[ch], bg = bin[Hq + ch];
        #pragma unroll
        for (int mi = 0; mi < 2; mi++) {
            float* c = acc[mi][ni];
            #pragma unroll
            for (int half = 0; half < 2; half++) {
                int row = m0 + wm + mi*16 + (lane >> 2) + half*8;
                float hid = c[2*half]   + bh;
                float gat = c[2*half+1] + bg;
                float z  = 1.f/(1.f + __expf(-gat));
                float cc = 1.f - z;
                float gt = (hid >= 0.f) ? (hid + 0.5f)
                                        : (1.f/(1.f + __expf(-hid)));
                g_c [(size_t)row*Hq + ch] = cc;
                g_zg[(size_t)row*Hq + ch] = z * gt;
            }
        }
    }
}

// ---------------------------------------------------------------------------
// K2-K4: chunked scan
// ---------------------------------------------------------------------------
__global__ void scan_chunks()
{
    int h = blockIdx.x*256 + threadIdx.x;
    int chunk = blockIdx.y, b = blockIdx.z;
    size_t base = ((size_t)b*Lq + (size_t)chunk*CLEN)*Hq + h;
    float A = 1.f, Bv = 0.f;
    #pragma unroll 8
    for (int t = 0; t < CLEN; t++) {
        float c = g_c[base], z = g_zg[base];
        Bv = c*Bv + z;
        A *= c;
        base += Hq;
    }
    size_t o = ((size_t)b*NCHUNK + chunk)*Hq + h;
    g_A[o] = A; g_Bc[o] = Bv;
}

__global__ void scan_tops()
{
    int g = blockIdx.x*256 + threadIdx.x;
    int b = g >> 10, hh = g & 1023;
    float hs = 0.f;
    size_t o = ((size_t)b*NCHUNK)*Hq + hh;
    for (int i = 0; i < NCHUNK; i++) {
        g_hs[o] = hs;
        hs = g_A[o]*hs + g_Bc[o];
        o += Hq;
    }
}

__global__ void scan_apply()
{
    int h = blockIdx.x*256 + threadIdx.x;
    int chunk = blockIdx.y, b = blockIdx.z;
    float hs = g_hs[((size_t)b*NCHUNK + chunk)*Hq + h];
    size_t base = ((size_t)b*Lq + (size_t)chunk*CLEN)*Hq + h;
    #pragma unroll 8
    for (int t = 0; t < CLEN; t++) {
        float c = g_c[base], z = g_zg[base];
        hs = c*hs + z;
        __half hi = __float2half_rn(hs);
        g_hh[base] = hi;
        g_hl[base] = __float2half_rn(hs - __half2float(hi));
        base += Hq;
    }
}

// ---------------------------------------------------------------------------
// K5: gemm2 (h @ W_out^T + b_out). Block 128m x 128n, K=1024.
// ---------------------------------------------------------------------------
__global__ __launch_bounds__(256, 2)
void gemm2_tc(const float* __restrict__ bout, float* __restrict__ Out)
{
    extern __shared__ char smem[];
    uint32_t su = s2u(smem);
    const int tid = threadIdx.x;
    const int lane = tid & 31;
    const int warp = tid >> 5;
    const int wm = (warp >> 1) * 32;
    const int wn = (warp & 1) * 64;
    const int m0 = blockIdx.x * 128;
    const int n0 = blockIdx.y * 128;
    const int NC = Hq / 32;   // 32

    float acc[2][8][4];
    #pragma unroll
    for (int i = 0; i < 2; i++)
        #pragma unroll
        for (int j = 0; j < 8; j++)
            #pragma unroll
            for (int q = 0; q < 4; q++) acc[i][j][q] = 0.f;

    auto stage = [&](int c) {
        uint32_t bb = su + (c % 3) * STAGE_B;
        int k0 = c * 32;
        #pragma unroll
        for (int i = 0; i < 2; i++) {
            int id = tid + 256 * i;
            int row = id >> 2, c8 = id & 3;
            uint32_t off = (uint32_t)(row * (LDK*2) + c8 * 16);
            size_t ai = (size_t)(m0 + row) * Hq + k0 + c8 * 8;
            cpa16(bb + OFF_AH + off, g_hh + ai);
            cpa16(bb + OFF_AL + off, g_hl + ai);
            size_t bi = (size_t)(n0 + row) * Hq + k0 + c8 * 8;
            cpa16(bb + OFF_BH + off, g_woh + bi);
        }
        CP_COMMIT();
    };

    stage(0); stage(1);
    for (int c = 0; c < NC; c++) {
        if (c + 1 < NC) { CP_WAIT1(); } else { CP_WAIT0(); }
        __syncthreads();
        if (c + 2 < NC) stage(c + 2);
        mma_stage(su + (c % 3) * STAGE_B, lane, wm, wn, acc);
    }

    #pragma unroll
    for (int ni = 0; ni < 8; ni++) {
        int nd = n0 + wn + ni*8 + 2*(lane & 3);
        float b0 = bout[nd], b1 = bout[nd+1];
        #pragma unroll
        for (int mi = 0; mi < 2; mi++) {
            float* c = acc[mi][ni];
            #pragma unroll
            for (int half = 0; half < 2; half++) {
                int row = m0 + wm + mi*16 + (lane >> 2) + half*8;
                float2 o;
                o.x = c[2*half]   + b0;
                o.y = c[2*half+1] + b1;
                *(float2*)(Out + (size_t)row*Dq + nd) = o;
            }
        }
    }
}

// ---------------------------------------------------------------------------
extern "C" void kernel_launch(void* const* d_in, const int* in_sizes, int n_in,
                              void* d_out, int out_size)
{
    const float *x = nullptr, *win = nullptr, *bin = nullptr,
                *wout = nullptr, *bout = nullptr;
    for (int i = 0; i < n_in; i++) {
        switch (in_sizes[i]) {
            case Bq*Lq*Dq: x    = (const float*)d_in[i]; break;
            case 2*Hq*Dq:  win  = (const float*)d_in[i]; break;
            case 2*Hq:     bin  = (const float*)d_in[i]; break;
            case Dq*Hq:    wout = (const float*)d_in[i]; break;
            case Dq:       bout = (const float*)d_in[i]; break;
        }
    }
    float* out = (float*)d_out;

    static bool attr_done = false;
    if (!attr_done) {
        cudaFuncSetAttribute(gemm1_tc, cudaFuncAttributeMaxDynamicSharedMemorySize, SMEM_TOTAL);
        cudaFuncSetAttribute(gemm2_tc, cudaFuncAttributeMaxDynamicSharedMemorySize, SMEM_TOTAL);
        attr_done = true;
    }

    __half *xh, *xl, *wih, *woh;
    cudaGetSymbolAddress((void**)&xh,  g_xh);
    cudaGetSymbolAddress((void**)&xl,  g_xl);
    cudaGetSymbolAddress((void**)&wih, g_wih);
    cudaGetSymbolAddress((void**)&woh, g_woh);

    split2_f16<<<(Mq*Dq/4 + 255)/256, 256>>>(x, xh, xl, Mq*Dq/4);
    conv_f16  <<<(2*Hq*Dq/4 + 255)/256, 256>>>(win, wih, 2*Hq*Dq/4);
    conv_f16  <<<(Dq*Hq/4 + 255)/256, 256>>>(wout, woh, Dq*Hq/4);

    gemm1_tc   <<<dim3(Mq/128, 2*Hq/128), 256, SMEM_TOTAL>>>(bin);
    scan_chunks<<<dim3(Hq/256, NCHUNK, Bq), 256>>>();
    scan_tops  <<<16, 256>>>();
    scan_apply <<<dim3(Hq/256, NCHUNK, Bq), 256>>>();
    gemm2_tc   <<<dim3(Mq/128, Dq/128), 256, SMEM_TOTAL>>>(bout, out);
}

// round 13
// speedup vs baseline: 3.8173x; 1.2849x over previous
#include <cuda_runtime.h>
#include <cuda_fp16.h>
#include <cstdint>

// Problem constants
#define Bq 4
#define Lq 8192
#define Dq 512
#define Hq 1024
#define Mq (Bq*Lq)        // 32768
#define NCHUNK 128
#define CLEN 64

// ---------------------------------------------------------------------------
// Scratch (device globals; allocation is forbidden)
// ---------------------------------------------------------------------------
__device__ float g_c [Bq*Lq*Hq];
__device__ float g_zg[Bq*Lq*Hq];
__device__ float g_A [Bq*NCHUNK*Hq];
__device__ float g_Bc[Bq*NCHUNK*Hq];
__device__ float g_hs[Bq*NCHUNK*Hq];
__device__ __half g_xh[(size_t)Mq*Dq];
__device__ __half g_wih[2*Hq*Dq];
__device__ __half g_woh[Dq*Hq];
__device__ __half g_hh[(size_t)Mq*Hq];

// ---------------------------------------------------------------------------
// PTX helpers
// ---------------------------------------------------------------------------
__device__ __forceinline__ uint32_t s2u(const void* p) {
    uint32_t a;
    asm("{ .reg .u64 t; cvta.to.shared.u64 t, %1; cvt.u32.u64 %0, t; }"
        : "=r"(a) : "l"(p));
    return a;
}
#define LDSM_X4(r0,r1,r2,r3,addr) \
    asm volatile("ldmatrix.sync.aligned.m8n8.x4.shared.b16 {%0,%1,%2,%3}, [%4];" \
        : "=r"(r0),"=r"(r1),"=r"(r2),"=r"(r3) : "r"(addr))

#define MMA_F16(c0,c1,c2,c3,a0,a1,a2,a3,b0,b1) \
    asm volatile("mma.sync.aligned.m16n8k16.row.col.f32.f16.f16.f32 " \
        "{%0,%1,%2,%3},{%4,%5,%6,%7},{%8,%9},{%0,%1,%2,%3};" \
        : "+f"(c0),"+f"(c1),"+f"(c2),"+f"(c3) \
        : "r"(a0),"r"(a1),"r"(a2),"r"(a3),"r"(b0),"r"(b1))

__device__ __forceinline__ void cpa16(uint32_t dst, const void* src) {
    asm volatile("cp.async.cg.shared.global [%0], [%1], 16;"
                 :: "r"(dst), "l"(src));
}
#define CP_COMMIT() asm volatile("cp.async.commit_group;")
#define CP_WAIT1()  asm volatile("cp.async.wait_group 1;")
#define CP_WAIT0()  asm volatile("cp.async.wait_group 0;")

// smem: BK=32, LDK=40 (80B rows, conflict-free ldmatrix). 2 tiles/stage (A, B).
#define LDK 40
#define TILE128 (128*LDK*2)            // 10240
#define OFF_A 0
#define OFF_B TILE128
#define STAGE_B (2*TILE128)            // 20480
#define SMEM_TOTAL (3*STAGE_B)         // 61440 -> 2 CTAs/SM

// ---------------------------------------------------------------------------
// convert: f32 -> fp16
// ---------------------------------------------------------------------------
__device__ __forceinline__ unsigned short hfu(__half h) {
    return *reinterpret_cast<unsigned short*>(&h);
}
__global__ void conv_f16(const float* __restrict__ s,
                         __half* __restrict__ hi, int n4)
{
    int i = blockIdx.x * blockDim.x + threadIdx.x;
    if (i >= n4) return;
    float4 v = ((const float4*)s)[i];
    __half hx = __float2half_rn(v.x), hy = __float2half_rn(v.y);
    __half hz = __float2half_rn(v.z), hw = __float2half_rn(v.w);
    uint2 H;
    H.x = (unsigned)hfu(hx) | ((unsigned)hfu(hy) << 16);
    H.y = (unsigned)hfu(hz) | ((unsigned)hfu(hw) << 16);
    ((uint2*)hi)[i] = H;
}

// ---------------------------------------------------------------------------
// MMA consume for one BK=32 stage. Warp tile 32m x 64n (2 m-frags x 8 n-frags).
// Single MMA per fragment pair.
// ---------------------------------------------------------------------------
__device__ __forceinline__ void mma_stage(uint32_t bb, int lane, int wm, int wn,
                                          float acc[2][8][4])
{
    #pragma unroll
    for (int ks = 0; ks < 2; ks++) {
        int kk = ks * 16;
        unsigned aH[2][4];
        {
            int ar = lane & 15;
            int ac = kk + 8 * (lane >> 4);
            #pragma unroll
            for (int mi = 0; mi < 2; mi++) {
                unsigned off = ((wm + mi*16 + ar) * LDK + ac) * 2;
                LDSM_X4(aH[mi][0],aH[mi][1],aH[mi][2],aH[mi][3], bb + OFF_A + off);
            }
        }
        unsigned bH[8][2];
        {
            int r  = lane & 7;
            int kc = kk + ((lane >> 3) & 1) * 8;
            int n8 = (lane >> 4) ? 8 : 0;
            #pragma unroll
            for (int p = 0; p < 4; p++) {
                unsigned off = ((wn + p*16 + n8 + r) * LDK + kc) * 2;
                LDSM_X4(bH[2*p][0],bH[2*p][1],bH[2*p+1][0],bH[2*p+1][1],
                        bb + OFF_B + off);
            }
        }
        #pragma unroll
        for (int mi = 0; mi < 2; mi++)
            #pragma unroll
            for (int ni = 0; ni < 8; ni++) {
                float* c = acc[mi][ni];
                MMA_F16(c[0],c[1],c[2],c[3],
                        aH[mi][0],aH[mi][1],aH[mi][2],aH[mi][3],
                        bH[ni][0],bH[ni][1]);
            }
    }
}

// ---------------------------------------------------------------------------
// K1: gemm1 (x @ W_in^T) + activation epilogue. Block 128m x 128col, K=512.
// Col j -> channel ch0+(j>>1); j&1: 0=hidden W row, 1=gate W row.
// Warps: 4 m-groups x 2 n-groups, warp tile 32x64. 3-stage, 1 sync/iter.
// ---------------------------------------------------------------------------
__global__ __launch_bounds__(256, 2)
void gemm1_tc(const float* __restrict__ bin)
{
    extern __shared__ char smem[];
    uint32_t su = s2u(smem);
    const int tid = threadIdx.x;
    const int lane = tid & 31;
    const int warp = tid >> 5;
    const int wm = (warp >> 1) * 32;
    const int wn = (warp & 1) * 64;
    const int m0 = blockIdx.x * 128;
    const int ch0 = blockIdx.y * 64;
    const int NC = Dq / 32;   // 16

    float acc[2][8][4];
    #pragma unroll
    for (int i = 0; i < 2; i++)
        #pragma unroll
        for (int j = 0; j < 8; j++)
            #pragma unroll
            for (int q = 0; q < 4; q++) acc[i][j][q] = 0.f;

    auto stage = [&](int c) {
        uint32_t bb = su + (c % 3) * STAGE_B;
        int k0 = c * 32;
        #pragma unroll
        for (int i = 0; i < 2; i++) {
            int id = tid + 256 * i;
            int row = id >> 2, c8 = id & 3;
            uint32_t off = (uint32_t)(row * (LDK*2) + c8 * 16);
            size_t ai = (size_t)(m0 + row) * Dq + k0 + c8 * 8;
            cpa16(bb + OFF_A + off, g_xh + ai);
            int wrow = (row & 1) ? (Hq + ch0 + (row >> 1)) : (ch0 + (row >> 1));
            size_t bi = (size_t)wrow * Dq + k0 + c8 * 8;
            cpa16(bb + OFF_B + off, g_wih + bi);
        }
        CP_COMMIT();
    };

    stage(0); stage(1);
    for (int c = 0; c < NC; c++) {
        if (c + 1 < NC) { CP_WAIT1(); } else { CP_WAIT0(); }
        __syncthreads();
        if (c + 2 < NC) stage(c + 2);
        mma_stage(su + (c % 3) * STAGE_B, lane, wm, wn, acc);
    }

    // epilogue: activations
    #pragma unroll
    for (int ni = 0; ni < 8; ni++) {
        int nloc = wn + ni*8 + 2*(lane & 3);
        int ch = ch0 + (nloc >> 1);
        float bh = bin[ch], bg = bin[Hq + ch];
        #pragma unroll
        for (int mi = 0; mi < 2; mi++) {
            float* c = acc[mi][ni];
            #pragma unroll
            for (int half = 0; half < 2; half++) {
                int row = m0 + wm + mi*16 + (lane >> 2) + half*8;
                float hid = c[2*half]   + bh;
                float gat = c[2*half+1] + bg;
                float z  = 1.f/(1.f + __expf(-gat));
                float cc = 1.f - z;
                float gt = (hid >= 0.f) ? (hid + 0.5f)
                                        : (1.f/(1.f + __expf(-hid)));
                g_c [(size_t)row*Hq + ch] = cc;
                g_zg[(size_t)row*Hq + ch] = z * gt;
            }
        }
    }
}

// ---------------------------------------------------------------------------
// K2-K4: chunked scan
// ---------------------------------------------------------------------------
__global__ void scan_chunks()
{
    int h = blockIdx.x*256 + threadIdx.x;
    int chunk = blockIdx.y, b = blockIdx.z;
    size_t base = ((size_t)b*Lq + (size_t)chunk*CLEN)*Hq + h;
    float A = 1.f, Bv = 0.f;
    #pragma unroll 8
    for (int t = 0; t < CLEN; t++) {
        float c = g_c[base], z = g_zg[base];
        Bv = c*Bv + z;
        A *= c;
        base += Hq;
    }
    size_t o = ((size_t)b*NCHUNK + chunk)*Hq + h;
    g_A[o] = A; g_Bc[o] = Bv;
}

__global__ void scan_tops()
{
    int g = blockIdx.x*256 + threadIdx.x;
    int b = g >> 10, hh = g & 1023;
    float hs = 0.f;
    size_t o = ((size_t)b*NCHUNK)*Hq + hh;
    for (int i = 0; i < NCHUNK; i++) {
        g_hs[o] = hs;
        hs = g_A[o]*hs + g_Bc[o];
        o += Hq;
    }
}

__global__ void scan_apply()
{
    int h = blockIdx.x*256 + threadIdx.x;
    int chunk = blockIdx.y, b = blockIdx.z;
    float hs = g_hs[((size_t)b*NCHUNK + chunk)*Hq + h];
    size_t base = ((size_t)b*Lq + (size_t)chunk*CLEN)*Hq + h;
    #pragma unroll 8
    for (int t = 0; t < CLEN; t++) {
        float c = g_c[base], z = g_zg[base];
        hs = c*hs + z;
        g_hh[base] = __float2half_rn(hs);
        base += Hq;
    }
}

// ---------------------------------------------------------------------------
// K5: gemm2 (h @ W_out^T + b_out). Block 128m x 128n, K=1024.
// ---------------------------------------------------------------------------
__global__ __launch_bounds__(256, 2)
void gemm2_tc(const float* __restrict__ bout, float* __restrict__ Out)
{
    extern __shared__ char smem[];
    uint32_t su = s2u(smem);
    const int tid = threadIdx.x;
    const int lane = tid & 31;
    const int warp = tid >> 5;
    const int wm = (warp >> 1) * 32;
    const int wn = (warp & 1) * 64;
    const int m0 = blockIdx.x * 128;
    const int n0 = blockIdx.y * 128;
    const int NC = Hq / 32;   // 32

    float acc[2][8][4];
    #pragma unroll
    for (int i = 0; i < 2; i++)
        #pragma unroll
        for (int j = 0; j < 8; j++)
            #pragma unroll
            for (int q = 0; q < 4; q++) acc[i][j][q] = 0.f;

    auto stage = [&](int c) {
        uint32_t bb = su + (c % 3) * STAGE_B;
        int k0 = c * 32;
        #pragma unroll
        for (int i = 0; i < 2; i++) {
            int id = tid + 256 * i;
            int row = id >> 2, c8 = id & 3;
            uint32_t off = (uint32_t)(row * (LDK*2) + c8 * 16);
            size_t ai = (size_t)(m0 + row) * Hq + k0 + c8 * 8;
            cpa16(bb + OFF_A + off, g_hh + ai);
            size_t bi = (size_t)(n0 + row) * Hq + k0 + c8 * 8;
            cpa16(bb + OFF_B + off, g_woh + bi);
        }
        CP_COMMIT();
    };

    stage(0); stage(1);
    for (int c = 0; c < NC; c++) {
        if (c + 1 < NC) { CP_WAIT1(); } else { CP_WAIT0(); }
        __syncthreads();
        if (c + 2 < NC) stage(c + 2);
        mma_stage(su + (c % 3) * STAGE_B, lane, wm, wn, acc);
    }

    #pragma unroll
    for (int ni = 0; ni < 8; ni++) {
        int nd = n0 + wn + ni*8 + 2*(lane & 3);
        float b0 = bout[nd], b1 = bout[nd+1];
        #pragma unroll
        for (int mi = 0; mi < 2; mi++) {
            float* c = acc[mi][ni];
            #pragma unroll
            for (int half = 0; half < 2; half++) {
                int row = m0 + wm + mi*16 + (lane >> 2) + half*8;
                float2 o;
                o.x = c[2*half]   + b0;
                o.y = c[2*half+1] + b1;
                *(float2*)(Out + (size_t)row*Dq + nd) = o;
            }
        }
    }
}

// ---------------------------------------------------------------------------
extern "C" void kernel_launch(void* const* d_in, const int* in_sizes, int n_in,
                              void* d_out, int out_size)
{
    const float *x = nullptr, *win = nullptr, *bin = nullptr,
                *wout = nullptr, *bout = nullptr;
    for (int i = 0; i < n_in; i++) {
        switch (in_sizes[i]) {
            case Bq*Lq*Dq: x    = (const float*)d_in[i]; break;
            case 2*Hq*Dq:  win  = (const float*)d_in[i]; break;
            case 2*Hq:     bin  = (const float*)d_in[i]; break;
            case Dq*Hq:    wout = (const float*)d_in[i]; break;
            case Dq:       bout = (const float*)d_in[i]; break;
        }
    }
    float* out = (float*)d_out;

    static bool attr_done = false;
    if (!attr_done) {
        cudaFuncSetAttribute(gemm1_tc, cudaFuncAttributeMaxDynamicSharedMemorySize, SMEM_TOTAL);
        cudaFuncSetAttribute(gemm2_tc, cudaFuncAttributeMaxDynamicSharedMemorySize, SMEM_TOTAL);
        attr_done = true;
    }

    __half *xh, *wih, *woh;
    cudaGetSymbolAddress((void**)&xh,  g_xh);
    cudaGetSymbolAddress((void**)&wih, g_wih);
    cudaGetSymbolAddress((void**)&woh, g_woh);

    conv_f16<<<(Mq*Dq/4 + 255)/256, 256>>>(x, xh, Mq*Dq/4);
    conv_f16<<<(2*Hq*Dq/4 + 255)/256, 256>>>(win, wih, 2*Hq*Dq/4);
    conv_f16<<<(Dq*Hq/4 + 255)/256, 256>>>(wout, woh, Dq*Hq/4);

    gemm1_tc   <<<dim3(Mq/128, 2*Hq/128), 256, SMEM_TOTAL>>>(bin);
    scan_chunks<<<dim3(Hq/256, NCHUNK, Bq), 256>>>();
    scan_tops  <<<16, 256>>>();
    scan_apply <<<dim3(Hq/256, NCHUNK, Bq), 256>>>();
    gemm2_tc   <<<dim3(Mq/128, Dq/128), 256, SMEM_TOTAL>>>(bout, out);
}